// round 2
// baseline (speedup 1.0000x reference)
#include <cuda_runtime.h>
#include <math.h>

#define NMAX 50000
#define EMAX 800000
#define ETOT (NMAX + EMAX)
#define FULLM 0xffffffffu
#define NBLK ((NMAX + 1023) / 1024)

// ---------------- scratch (static device globals: no allocation allowed) ----
__device__ int   d_is64;
__device__ int   d_deg[NMAX];
__device__ int   d_rowptr[NMAX + 1];
__device__ int   d_cursor[NMAX];
__device__ int   d_bsum[NBLK];
__device__ int   d_boff[NBLK];
__device__ int   d_col[ETOT];
__device__ float d_hA[NMAX * 128];   // feature buffer (h of current layer)
__device__ float d_hB[NMAX * 128];   // activation buffer (z of current layer)
__device__ float d_as[NMAX * 4];
__device__ float d_ad[NMAX * 4];
__device__ float d_h3[NMAX];
__device__ float d_as3[NMAX];
__device__ float d_ad3[NMAX];

// ---------------- helpers ---------------------------------------------------
__device__ __forceinline__ float lrelu(float e) { return e > 0.f ? e : 0.2f * e; }

__device__ __forceinline__ float wredsum(float v) {
#pragma unroll
    for (int o = 16; o; o >>= 1) v += __shfl_xor_sync(FULLM, v, o);
    return v;
}
__device__ __forceinline__ float wredmax(float v) {
#pragma unroll
    for (int o = 16; o; o >>= 1) v = fmaxf(v, __shfl_xor_sync(FULLM, v, o));
    return v;
}
__device__ __forceinline__ int wincl(int x, int lane) {
#pragma unroll
    for (int o = 1; o < 32; o <<= 1) {
        int t = __shfl_up_sync(FULLM, x, o);
        if (lane >= o) x += t;
    }
    return x;
}
__device__ __forceinline__ float comp4(float4 v, int h) {
    float r = v.x;
    r = (h == 1) ? v.y : r;
    r = (h == 2) ? v.z : r;
    r = (h == 3) ? v.w : r;
    return r;
}

// ---------------- dtype detect (int32 vs int64 edge_index) ------------------
__global__ void detect_k(const void* ei) {
    if (threadIdx.x == 0 && blockIdx.x == 0) {
        const int* p = (const int*)ei;
        int is64 = 1;
        for (int i = 0; i < 256; i++) {
            if (p[2 * i + 1] != 0) { is64 = 0; break; }
        }
        d_is64 = is64;
    }
}

// ---------------- CSR build -------------------------------------------------
__global__ void zero_k(int N) {
    int i = blockIdx.x * blockDim.x + threadIdx.x;
    if (i < N) d_deg[i] = 0;
}

__global__ void hist_k(const void* ei, int E, int N) {
    int e = blockIdx.x * blockDim.x + threadIdx.x;
    int tot = E + N;
    if (e >= tot) return;
    int dst;
    if (e < E) {
        if (d_is64) dst = (int)((const long long*)ei)[(long long)E + e];
        else        dst = ((const int*)ei)[E + e];
    } else {
        dst = e - E;  // self loop
    }
    atomicAdd(&d_deg[dst], 1);
}

// phase 1: per-block inclusive scan (warp shuffles), emit block sums
__global__ void scan1_k(int N) {
    __shared__ int wsum[32];
    int i = blockIdx.x * 1024 + threadIdx.x;
    int lane = threadIdx.x & 31, wid = threadIdx.x >> 5;
    int v = (i < N) ? d_deg[i] : 0;
    int x = wincl(v, lane);
    if (lane == 31) wsum[wid] = x;
    __syncthreads();
    if (wid == 0) wsum[lane] = wincl(wsum[lane], lane);
    __syncthreads();
    int incl = x + (wid ? wsum[wid - 1] : 0);
    if (i < N) d_rowptr[i + 1] = incl;     // block-local for now
    if (threadIdx.x == 1023) d_bsum[blockIdx.x] = incl;
}

// phase 2: exclusive scan of block sums (single warp, nb <= NBLK)
__global__ void scan2_k(int nb) {
    int lane = threadIdx.x;
    int carry = 0;
    for (int base = 0; base < nb; base += 32) {
        int idx = base + lane;
        int v = (idx < nb) ? d_bsum[idx] : 0;
        int x = wincl(v, lane);
        if (idx < nb) d_boff[idx] = carry + x - v;
        carry += __shfl_sync(FULLM, x, 31);
    }
}

// phase 3: apply block offsets, derive cursors
__global__ void scan3_k(int N) {
    int i = blockIdx.x * 1024 + threadIdx.x;
    if (i >= N) return;
    int r = d_rowptr[i + 1] + d_boff[blockIdx.x];
    d_rowptr[i + 1] = r;
    d_cursor[i] = r - d_deg[i];
    if (i == 0) d_rowptr[0] = 0;
}

__global__ void scatter_k(const void* ei, int E, int N) {
    int e = blockIdx.x * blockDim.x + threadIdx.x;
    int tot = E + N;
    if (e >= tot) return;
    int src, dst;
    if (e < E) {
        if (d_is64) {
            const long long* p = (const long long*)ei;
            src = (int)p[e];
            dst = (int)p[(long long)E + e];
        } else {
            const int* p = (const int*)ei;
            src = p[e];
            dst = p[E + e];
        }
    } else {
        src = dst = e - E;
    }
    int pos = atomicAdd(&d_cursor[dst], 1);
    d_col[pos] = src;
}

// ---------------- layer 1 feature: h1 = x @ W1 (Fin=1), alphas --------------
__global__ void l1_feat_k(const float* __restrict__ x, const float* __restrict__ W1,
                          const float* __restrict__ as1, const float* __restrict__ ad1,
                          float* __restrict__ h_out, int N) {
    int n = blockIdx.x;
    if (n >= N) return;
    int j = threadIdx.x;  // 0..127, warp = head
    float xv = x[n];
    float h = xv * W1[j];
    h_out[n * 128 + j] = h;
    float ps = wredsum(h * as1[j]);
    float pd = wredsum(h * ad1[j]);
    if ((j & 31) == 0) {
        d_as[n * 4 + (j >> 5)] = ps;
        d_ad[n * 4 + (j >> 5)] = pd;
    }
}

// ---------------- layer 2 feature: h2 = z1 @ W2 (128x128), alphas -----------
// persistent blocks, W2 resident in smem, 8-node register blocking
__global__ void gemm_k(const float* __restrict__ zin, const float* __restrict__ W2,
                       const float* __restrict__ as2, const float* __restrict__ ad2,
                       float* __restrict__ h_out, int N) {
    extern __shared__ float smem[];        // [128*128 W][128*8 zt]
    float* Wsm = smem;
    float* zt  = smem + 128 * 128;
    int tid = threadIdx.x;                 // 128 threads

    // load W2 once per block
    for (int t = tid; t < 128 * 128 / 4; t += 128)
        ((float4*)Wsm)[t] = ((const float4*)W2)[t];
    __syncthreads();

    float asj = as2[tid];
    float adj = ad2[tid];
    int lane = tid & 31, head = tid >> 5;

    for (int g = blockIdx.x * 8; g < N; g += gridDim.x * 8) {
        // zt[k*8+m] = z[(g+m)*128 + k], k = tid
#pragma unroll
        for (int m = 0; m < 8; m++) {
            int node = g + m;
            zt[tid * 8 + m] = (node < N) ? zin[node * 128 + tid] : 0.f;
        }
        __syncthreads();

        float acc[8] = {0.f, 0.f, 0.f, 0.f, 0.f, 0.f, 0.f, 0.f};
#pragma unroll 4
        for (int k = 0; k < 128; k++) {
            float w = Wsm[k * 128 + tid];
            float4 z0 = ((const float4*)zt)[k * 2];
            float4 z1 = ((const float4*)zt)[k * 2 + 1];
            acc[0] = fmaf(z0.x, w, acc[0]);
            acc[1] = fmaf(z0.y, w, acc[1]);
            acc[2] = fmaf(z0.z, w, acc[2]);
            acc[3] = fmaf(z0.w, w, acc[3]);
            acc[4] = fmaf(z1.x, w, acc[4]);
            acc[5] = fmaf(z1.y, w, acc[5]);
            acc[6] = fmaf(z1.z, w, acc[6]);
            acc[7] = fmaf(z1.w, w, acc[7]);
        }
#pragma unroll
        for (int m = 0; m < 8; m++) {
            int node = g + m;
            float ps = wredsum(acc[m] * asj);
            float pd = wredsum(acc[m] * adj);
            if (node < N) {
                h_out[node * 128 + tid] = acc[m];
                if (lane == 0) {
                    d_as[node * 4 + head] = ps;
                    d_ad[node * 4 + head] = pd;
                }
            }
        }
        __syncthreads();
    }
}

// ---------------- GAT aggregation (layers 1 & 2), warp per dst node ---------
__global__ void agg_k(const float* __restrict__ h_in,
                      const float* __restrict__ bias,
                      float* __restrict__ z_out,
                      const float* __restrict__ w3,
                      const float* __restrict__ a3s, const float* __restrict__ a3d,
                      int apply_elu, int store_z, int N) {
    int w = (blockIdx.x * blockDim.x + threadIdx.x) >> 5;
    if (w >= N) return;
    int lane = threadIdx.x & 31;
    int start = d_rowptr[w], end = d_rowptr[w + 1];

    float4 adv = ((const float4*)d_ad)[w];

    // pass 1: max per head
    float m0 = -1e30f, m1 = -1e30f, m2 = -1e30f, m3 = -1e30f;
    for (int i = start + lane; i < end; i += 32) {
        int s = d_col[i];
        float4 av = ((const float4*)d_as)[s];
        m0 = fmaxf(m0, lrelu(av.x + adv.x));
        m1 = fmaxf(m1, lrelu(av.y + adv.y));
        m2 = fmaxf(m2, lrelu(av.z + adv.z));
        m3 = fmaxf(m3, lrelu(av.w + adv.w));
    }
    m0 = wredmax(m0); m1 = wredmax(m1); m2 = wredmax(m2); m3 = wredmax(m3);

    // pass 2: sum of exp per head
    float s0 = 0.f, s1 = 0.f, s2 = 0.f, s3 = 0.f;
    for (int i = start + lane; i < end; i += 32) {
        int s = d_col[i];
        float4 av = ((const float4*)d_as)[s];
        s0 += __expf(lrelu(av.x + adv.x) - m0);
        s1 += __expf(lrelu(av.y + adv.y) - m1);
        s2 += __expf(lrelu(av.z + adv.z) - m2);
        s3 += __expf(lrelu(av.w + adv.w) - m3);
    }
    s0 = wredsum(s0); s1 = wredsum(s1); s2 = wredsum(s2); s3 = wredsum(s3);

    int myh = lane >> 3;  // lane holds channels 4*lane..4*lane+3, all in head lane/8
    float mh   = comp4(make_float4(m0, m1, m2, m3), myh);
    float invh = comp4(make_float4(1.f / s0, 1.f / s1, 1.f / s2, 1.f / s3), myh);
    float adh  = comp4(adv, myh);

    // pass 3: weighted sum of source features
    float4 acc = make_float4(0.f, 0.f, 0.f, 0.f);
#pragma unroll 2
    for (int i = start; i < end; i++) {
        int s = d_col[i];
        float4 av = ((const float4*)d_as)[s];
        float wgt = __expf(lrelu(comp4(av, myh) + adh) - mh) * invh;
        float4 hv = ((const float4*)h_in)[s * 32 + lane];
        acc.x = fmaf(wgt, hv.x, acc.x);
        acc.y = fmaf(wgt, hv.y, acc.y);
        acc.z = fmaf(wgt, hv.z, acc.z);
        acc.w = fmaf(wgt, hv.w, acc.w);
    }

    float4 bv = ((const float4*)bias)[lane];
    float4 v = make_float4(acc.x + bv.x, acc.y + bv.y, acc.z + bv.z, acc.w + bv.w);
    if (apply_elu) {
        v.x = v.x > 0.f ? v.x : expm1f(v.x);
        v.y = v.y > 0.f ? v.y : expm1f(v.y);
        v.z = v.z > 0.f ? v.z : expm1f(v.z);
        v.w = v.w > 0.f ? v.w : expm1f(v.w);
    }
    if (store_z) ((float4*)z_out)[w * 32 + lane] = v;

    if (w3) {  // fused layer-3 feature: h3 = v . W3, alphas
        float4 w4 = ((const float4*)w3)[lane];
        float p = v.x * w4.x + v.y * w4.y + v.z * w4.z + v.w * w4.w;
        p = wredsum(p);
        if (lane == 0) {
            d_h3[w]  = p;
            d_as3[w] = p * a3s[0];
            d_ad3[w] = p * a3d[0];
        }
    }
}

// ---------------- layer 3 aggregation (H=1, C=1), warp per dst node ---------
__global__ void agg3_k(const float* __restrict__ b3, float* __restrict__ out, int N) {
    int w = (blockIdx.x * blockDim.x + threadIdx.x) >> 5;
    if (w >= N) return;
    int lane = threadIdx.x & 31;
    int start = d_rowptr[w], end = d_rowptr[w + 1];
    float adn = d_ad3[w];

    float m = -1e30f;
    for (int i = start + lane; i < end; i += 32) {
        int s = d_col[i];
        m = fmaxf(m, lrelu(d_as3[s] + adn));
    }
    m = wredmax(m);

    float ss = 0.f, ws = 0.f;
    for (int i = start + lane; i < end; i += 32) {
        int s = d_col[i];
        float wv = __expf(lrelu(d_as3[s] + adn) - m);
        ss += wv;
        ws += wv * d_h3[s];
    }
    ss = wredsum(ss);
    ws = wredsum(ws);
    if (lane == 0) out[w] = ws / ss + b3[0];
}

// ---------------- host launcher ---------------------------------------------
extern "C" void kernel_launch(void* const* d_in, const int* in_sizes, int n_in,
                              void* d_out, int out_size) {
    const float* x   = (const float*)d_in[0];
    const void*  ei  = d_in[1];
    const float* W1  = (const float*)d_in[2];
    const float* as1 = (const float*)d_in[3];
    const float* ad1 = (const float*)d_in[4];
    const float* b1  = (const float*)d_in[5];
    const float* W2  = (const float*)d_in[6];
    const float* as2 = (const float*)d_in[7];
    const float* ad2 = (const float*)d_in[8];
    const float* b2  = (const float*)d_in[9];
    const float* W3  = (const float*)d_in[10];
    const float* a3s = (const float*)d_in[11];
    const float* a3d = (const float*)d_in[12];
    const float* b3  = (const float*)d_in[13];
    float* out = (float*)d_out;

    int N = in_sizes[0];       // IN_C = 1
    int E = in_sizes[1] / 2;   // element count, dtype-independent
    if (N > NMAX) N = NMAX;
    if (E > EMAX) E = EMAX;
    int tot = E + N;
    int nb = (N + 1023) / 1024;

    float* hA; cudaGetSymbolAddress((void**)&hA, d_hA);
    float* hB; cudaGetSymbolAddress((void**)&hB, d_hB);

    detect_k<<<1, 32>>>(ei);
    zero_k<<<(N + 255) / 256, 256>>>(N);
    hist_k<<<(tot + 255) / 256, 256>>>(ei, E, N);
    scan1_k<<<nb, 1024>>>(N);
    scan2_k<<<1, 32>>>(nb);
    scan3_k<<<nb, 1024>>>(N);
    scatter_k<<<(tot + 255) / 256, 256>>>(ei, E, N);

    // layer 1
    l1_feat_k<<<N, 128>>>(x, W1, as1, ad1, hA, N);
    int agg_blocks = (N * 32 + 255) / 256;
    agg_k<<<agg_blocks, 256>>>(hA, b1, hB, nullptr, nullptr, nullptr,
                               /*elu=*/1, /*store_z=*/1, N);

    // layer 2 (fused layer-3 feature in agg epilogue)
    size_t smem = (128 * 128 + 128 * 8) * sizeof(float);
    cudaFuncSetAttribute(gemm_k, cudaFuncAttributeMaxDynamicSharedMemorySize, (int)smem);
    gemm_k<<<444, 128, smem>>>(hB, W2, as2, ad2, hA, N);
    agg_k<<<agg_blocks, 256>>>(hA, b2, nullptr, W3, a3s, a3d,
                               /*elu=*/1, /*store_z=*/0, N);

    // layer 3
    agg3_k<<<agg_blocks, 256>>>(b3, out, N);
}

// round 3
// speedup vs baseline: 1.7248x; 1.7248x over previous
#include <cuda_runtime.h>
#include <math.h>

#define NMAX 50000
#define EMAX 800000
#define ETOT (NMAX + EMAX)
#define FULLM 0xffffffffu
#define NBLK ((NMAX + 1023) / 1024)

// ---------------- scratch (static device globals: no allocation allowed) ----
__device__ int   d_is64;
__device__ int   d_deg[NMAX];
__device__ int   d_rowptr[NMAX + 1];
__device__ int   d_cursor[NMAX];
__device__ int   d_bsum[NBLK];
__device__ int   d_boff[NBLK];
__device__ int   d_col[ETOT];
__device__ float d_hA[NMAX * 128];   // feature buffer (h of current layer)
__device__ float d_hB[NMAX * 128];   // activation buffer (z of current layer)
__device__ float d_as[NMAX * 4];
__device__ float d_ad[NMAX * 4];
__device__ float d_h3[NMAX];
__device__ float d_as3[NMAX];
__device__ float d_ad3[NMAX];

// ---------------- helpers ---------------------------------------------------
__device__ __forceinline__ float lrelu(float e) { return e > 0.f ? e : 0.2f * e; }

__device__ __forceinline__ float wredsum(float v) {
#pragma unroll
    for (int o = 16; o; o >>= 1) v += __shfl_xor_sync(FULLM, v, o);
    return v;
}
__device__ __forceinline__ int wincl(int x, int lane) {
#pragma unroll
    for (int o = 1; o < 32; o <<= 1) {
        int t = __shfl_up_sync(FULLM, x, o);
        if (lane >= o) x += t;
    }
    return x;
}
__device__ __forceinline__ float comp4(float4 v, int h) {
    float r = v.x;
    r = (h == 1) ? v.y : r;
    r = (h == 2) ? v.z : r;
    r = (h == 3) ? v.w : r;
    return r;
}

// ---------------- dtype detect (int32 vs int64 edge_index) ------------------
__global__ void detect_k(const void* ei) {
    int lane = threadIdx.x;
    const int* p = (const int*)ei;
    int bad = 0;
#pragma unroll
    for (int i = 0; i < 8; i++) {
        int idx = lane + i * 32;
        bad |= (p[2 * idx + 1] != 0);
    }
    unsigned any = __ballot_sync(FULLM, bad);
    if (lane == 0) d_is64 = (any == 0) ? 1 : 0;
}

// ---------------- CSR build -------------------------------------------------
__global__ void zero_k(int N) {
    int i = blockIdx.x * blockDim.x + threadIdx.x;
    if (i < N) d_deg[i] = 0;
}

__global__ void hist_k(const void* ei, int E, int N) {
    int e = blockIdx.x * blockDim.x + threadIdx.x;
    int tot = E + N;
    if (e >= tot) return;
    int dst;
    if (e < E) {
        if (d_is64) dst = (int)((const long long*)ei)[(long long)E + e];
        else        dst = ((const int*)ei)[E + e];
    } else {
        dst = e - E;  // self loop
    }
    atomicAdd(&d_deg[dst], 1);
}

// phase 1: per-block inclusive scan (warp shuffles), emit block sums
__global__ void scan1_k(int N) {
    __shared__ int wsum[32];
    int i = blockIdx.x * 1024 + threadIdx.x;
    int lane = threadIdx.x & 31, wid = threadIdx.x >> 5;
    int v = (i < N) ? d_deg[i] : 0;
    int x = wincl(v, lane);
    if (lane == 31) wsum[wid] = x;
    __syncthreads();
    if (wid == 0) wsum[lane] = wincl(wsum[lane], lane);
    __syncthreads();
    int incl = x + (wid ? wsum[wid - 1] : 0);
    if (i < N) d_rowptr[i + 1] = incl;     // block-local for now
    if (threadIdx.x == 1023) d_bsum[blockIdx.x] = incl;
}

// phase 2: exclusive scan of block sums (single warp)
__global__ void scan2_k(int nb) {
    int lane = threadIdx.x;
    int carry = 0;
    for (int base = 0; base < nb; base += 32) {
        int idx = base + lane;
        int v = (idx < nb) ? d_bsum[idx] : 0;
        int x = wincl(v, lane);
        if (idx < nb) d_boff[idx] = carry + x - v;
        carry += __shfl_sync(FULLM, x, 31);
    }
}

// phase 3: apply block offsets, derive cursors
__global__ void scan3_k(int N) {
    int i = blockIdx.x * 1024 + threadIdx.x;
    if (i >= N) return;
    int r = d_rowptr[i + 1] + d_boff[blockIdx.x];
    d_rowptr[i + 1] = r;
    d_cursor[i] = r - d_deg[i];
    if (i == 0) d_rowptr[0] = 0;
}

__global__ void scatter_k(const void* ei, int E, int N) {
    int e = blockIdx.x * blockDim.x + threadIdx.x;
    int tot = E + N;
    if (e >= tot) return;
    int src, dst;
    if (e < E) {
        if (d_is64) {
            const long long* p = (const long long*)ei;
            src = (int)p[e];
            dst = (int)p[(long long)E + e];
        } else {
            const int* p = (const int*)ei;
            src = p[e];
            dst = p[E + e];
        }
    } else {
        src = dst = e - E;
    }
    int pos = atomicAdd(&d_cursor[dst], 1);
    d_col[pos] = src;
}

// ---------------- layer 1 feature: h1 = x @ W1 (Fin=1), alphas --------------
__global__ void l1_feat_k(const float* __restrict__ x, const float* __restrict__ W1,
                          const float* __restrict__ as1, const float* __restrict__ ad1,
                          float* __restrict__ h_out, int N) {
    int n = blockIdx.x;
    if (n >= N) return;
    int j = threadIdx.x;  // 0..127, warp = head
    float xv = x[n];
    float h = xv * W1[j];
    h_out[n * 128 + j] = h;
    float ps = wredsum(h * as1[j]);
    float pd = wredsum(h * ad1[j]);
    if ((j & 31) == 0) {
        d_as[n * 4 + (j >> 5)] = ps;
        d_ad[n * 4 + (j >> 5)] = pd;
    }
}

// ---------------- layer 2 feature: h2 = z1 @ W2 (128x128), alphas -----------
// 256 threads: thread = (c=channel-quad 0..31, g=node-group 0..7).
// Each thread computes 4 channels x 8 nodes = 32 FMA per k step.
// W2 (64KB) + transposed z tile (64 nodes, pad 68) in dynamic smem.
#define ZPAD 68
__global__ void gemm_k(const float* __restrict__ zin, const float* __restrict__ W2,
                       const float* __restrict__ as2, const float* __restrict__ ad2,
                       float* __restrict__ h_out, int N) {
    extern __shared__ float smem[];             // [128*128 W][128*ZPAD zt]
    float* Wsm = smem;
    float* zt  = smem + 128 * 128;
    int tid = threadIdx.x;                      // 256 threads
    int c = tid & 31;                           // channels 4c..4c+3
    int g = tid >> 5;                           // node group (warp), nodes g*8..g*8+7
    int head = c >> 3;

    for (int t = tid; t < 128 * 128 / 4; t += 256)
        ((float4*)Wsm)[t] = ((const float4*)W2)[t];

    float4 as4 = ((const float4*)as2)[c];
    float4 ad4 = ((const float4*)ad2)[c];

    for (int tile = blockIdx.x * 64; tile < N; tile += gridDim.x * 64) {
        __syncthreads();   // previous-iter reads done before overwrite
        // zt[k*ZPAD + node] = z[(tile+node)*128 + k]
        for (int t = tid; t < 64 * 128; t += 256) {
            int node = t >> 7;
            int k = t & 127;
            int gn = tile + node;
            zt[k * ZPAD + node] = (gn < N) ? zin[gn * 128 + k] : 0.f;
        }
        __syncthreads();

        float4 acc[8];
#pragma unroll
        for (int m = 0; m < 8; m++) acc[m] = make_float4(0.f, 0.f, 0.f, 0.f);

#pragma unroll 2
        for (int k = 0; k < 128; k++) {
            float4 w4 = ((const float4*)(Wsm + k * 128))[c];
            const float* zr = zt + k * ZPAD + g * 8;
            float4 z0 = *((const float4*)zr);
            float4 z1 = *((const float4*)(zr + 4));
            float zm[8] = {z0.x, z0.y, z0.z, z0.w, z1.x, z1.y, z1.z, z1.w};
#pragma unroll
            for (int m = 0; m < 8; m++) {
                acc[m].x = fmaf(zm[m], w4.x, acc[m].x);
                acc[m].y = fmaf(zm[m], w4.y, acc[m].y);
                acc[m].z = fmaf(zm[m], w4.z, acc[m].z);
                acc[m].w = fmaf(zm[m], w4.w, acc[m].w);
            }
        }

#pragma unroll
        for (int m = 0; m < 8; m++) {
            int node = tile + g * 8 + m;
            float ps = acc[m].x * as4.x + acc[m].y * as4.y + acc[m].z * as4.z + acc[m].w * as4.w;
            float pd = acc[m].x * ad4.x + acc[m].y * ad4.y + acc[m].z * ad4.z + acc[m].w * ad4.w;
            // reduce within 8-lane head group
#pragma unroll
            for (int o = 4; o; o >>= 1) {
                ps += __shfl_xor_sync(FULLM, ps, o);
                pd += __shfl_xor_sync(FULLM, pd, o);
            }
            if (node < N) {
                ((float4*)(h_out + node * 128))[c] = acc[m];
                if ((c & 7) == 0) {
                    d_as[node * 4 + head] = ps;
                    d_ad[node * 4 + head] = pd;
                }
            }
        }
    }
}

// ---------------- GAT aggregation (layers 1 & 2), warp per dst node ---------
// no max pass: exp(e)/sum(exp(e)) is mathematically identical to the
// max-subtracted softmax; |e| << 88 here so no overflow.
__global__ void agg_k(const float* __restrict__ h_in,
                      const float* __restrict__ bias,
                      float* __restrict__ z_out,
                      const float* __restrict__ w3,
                      const float* __restrict__ a3s, const float* __restrict__ a3d,
                      int apply_elu, int store_z, int N) {
    int w = (blockIdx.x * blockDim.x + threadIdx.x) >> 5;
    if (w >= N) return;
    int lane = threadIdx.x & 31;
    int start = d_rowptr[w], end = d_rowptr[w + 1];

    float4 adv = ((const float4*)d_ad)[w];

    // pass 1: softmax denominators per head
    float s0 = 0.f, s1 = 0.f, s2 = 0.f, s3 = 0.f;
    for (int i = start + lane; i < end; i += 32) {
        int s = d_col[i];
        float4 av = ((const float4*)d_as)[s];
        s0 += __expf(lrelu(av.x + adv.x));
        s1 += __expf(lrelu(av.y + adv.y));
        s2 += __expf(lrelu(av.z + adv.z));
        s3 += __expf(lrelu(av.w + adv.w));
    }
    s0 = wredsum(s0); s1 = wredsum(s1); s2 = wredsum(s2); s3 = wredsum(s3);

    int myh = lane >> 3;  // lane holds channels 4*lane..4*lane+3, head = lane/8
    float invh = comp4(make_float4(1.f / s0, 1.f / s1, 1.f / s2, 1.f / s3), myh);
    float adh  = comp4(adv, myh);

    // pass 2: weighted sum of source features
    float4 acc = make_float4(0.f, 0.f, 0.f, 0.f);
#pragma unroll 2
    for (int i = start; i < end; i++) {
        int s = d_col[i];
        float4 av = ((const float4*)d_as)[s];
        float wgt = __expf(lrelu(comp4(av, myh) + adh)) * invh;
        float4 hv = ((const float4*)h_in)[s * 32 + lane];
        acc.x = fmaf(wgt, hv.x, acc.x);
        acc.y = fmaf(wgt, hv.y, acc.y);
        acc.z = fmaf(wgt, hv.z, acc.z);
        acc.w = fmaf(wgt, hv.w, acc.w);
    }

    float4 bv = ((const float4*)bias)[lane];
    float4 v = make_float4(acc.x + bv.x, acc.y + bv.y, acc.z + bv.z, acc.w + bv.w);
    if (apply_elu) {
        v.x = v.x > 0.f ? v.x : expm1f(v.x);
        v.y = v.y > 0.f ? v.y : expm1f(v.y);
        v.z = v.z > 0.f ? v.z : expm1f(v.z);
        v.w = v.w > 0.f ? v.w : expm1f(v.w);
    }
    if (store_z) ((float4*)z_out)[w * 32 + lane] = v;

    if (w3) {  // fused layer-3 feature: h3 = v . W3, alphas
        float4 w4 = ((const float4*)w3)[lane];
        float p = v.x * w4.x + v.y * w4.y + v.z * w4.z + v.w * w4.w;
        p = wredsum(p);
        if (lane == 0) {
            d_h3[w]  = p;
            d_as3[w] = p * a3s[0];
            d_ad3[w] = p * a3d[0];
        }
    }
}

// ---------------- layer 3 aggregation (H=1, C=1), warp per dst node ---------
__global__ void agg3_k(const float* __restrict__ b3, float* __restrict__ out, int N) {
    int w = (blockIdx.x * blockDim.x + threadIdx.x) >> 5;
    if (w >= N) return;
    int lane = threadIdx.x & 31;
    int start = d_rowptr[w], end = d_rowptr[w + 1];
    float adn = d_ad3[w];

    float ss = 0.f, ws = 0.f;
    for (int i = start + lane; i < end; i += 32) {
        int s = d_col[i];
        float wv = __expf(lrelu(d_as3[s] + adn));
        ss += wv;
        ws += wv * d_h3[s];
    }
    ss = wredsum(ss);
    ws = wredsum(ws);
    if (lane == 0) out[w] = ws / ss + b3[0];
}

// ---------------- host launcher ---------------------------------------------
extern "C" void kernel_launch(void* const* d_in, const int* in_sizes, int n_in,
                              void* d_out, int out_size) {
    const float* x   = (const float*)d_in[0];
    const void*  ei  = d_in[1];
    const float* W1  = (const float*)d_in[2];
    const float* as1 = (const float*)d_in[3];
    const float* ad1 = (const float*)d_in[4];
    const float* b1  = (const float*)d_in[5];
    const float* W2  = (const float*)d_in[6];
    const float* as2 = (const float*)d_in[7];
    const float* ad2 = (const float*)d_in[8];
    const float* b2  = (const float*)d_in[9];
    const float* W3  = (const float*)d_in[10];
    const float* a3s = (const float*)d_in[11];
    const float* a3d = (const float*)d_in[12];
    const float* b3  = (const float*)d_in[13];
    float* out = (float*)d_out;

    int N = in_sizes[0];       // IN_C = 1
    int E = in_sizes[1] / 2;   // element count, dtype-independent
    if (N > NMAX) N = NMAX;
    if (E > EMAX) E = EMAX;
    int tot = E + N;
    int nb = (N + 1023) / 1024;

    float* hA; cudaGetSymbolAddress((void**)&hA, d_hA);
    float* hB; cudaGetSymbolAddress((void**)&hB, d_hB);

    detect_k<<<1, 32>>>(ei);
    zero_k<<<(N + 255) / 256, 256>>>(N);
    hist_k<<<(tot + 255) / 256, 256>>>(ei, E, N);
    scan1_k<<<nb, 1024>>>(N);
    scan2_k<<<1, 32>>>(nb);
    scan3_k<<<nb, 1024>>>(N);
    scatter_k<<<(tot + 255) / 256, 256>>>(ei, E, N);

    // layer 1
    l1_feat_k<<<N, 128>>>(x, W1, as1, ad1, hA, N);
    int agg_blocks = (N * 32 + 255) / 256;
    agg_k<<<agg_blocks, 256>>>(hA, b1, hB, nullptr, nullptr, nullptr,
                               /*elu=*/1, /*store_z=*/1, N);

    // layer 2 (fused layer-3 feature in agg epilogue)
    size_t smem = (128 * 128 + 128 * ZPAD) * sizeof(float);
    cudaFuncSetAttribute(gemm_k, cudaFuncAttributeMaxDynamicSharedMemorySize, (int)smem);
    gemm_k<<<296, 256, smem>>>(hB, W2, as2, ad2, hA, N);
    agg_k<<<agg_blocks, 256>>>(hA, b2, nullptr, W3, a3s, a3d,
                               /*elu=*/1, /*store_z=*/0, N);

    // layer 3
    agg3_k<<<agg_blocks, 256>>>(b3, out, N);
}

// round 6
// speedup vs baseline: 2.5008x; 1.4499x over previous
#include <cuda_runtime.h>
#include <math.h>

#define NMAX 50000
#define EMAX 800000
#define ETOT (NMAX + EMAX)
#define FULLM 0xffffffffu
#define NBLK ((NMAX + 1023) / 1024)

// ---------------- scratch (static device globals: no allocation allowed) ----
__device__ int   d_is64;
__device__ int   d_deg[NMAX];
__device__ int   d_rowptr[NMAX + 1];
__device__ int   d_cursor[NMAX];
__device__ int   d_bsum[NBLK];
__device__ int   d_boff[NBLK];
__device__ int   d_col[ETOT];
__device__ float d_hA[NMAX * 128];   // h2 feature buffer
__device__ float d_hB[NMAX * 128];   // z1 activation buffer
__device__ float d_as[NMAX * 4];
__device__ float d_ad[NMAX * 4];
__device__ float d_cs[4];            // layer1 rank-1 alpha coefficients
__device__ float d_cd[4];
__device__ float d_h3[NMAX];
__device__ float d_as3[NMAX];
__device__ float d_ad3[NMAX];

// ---------------- helpers ---------------------------------------------------
__device__ __forceinline__ float lrelu(float e) { return e > 0.f ? e : 0.2f * e; }

__device__ __forceinline__ float wredsum(float v) {
#pragma unroll
    for (int o = 16; o; o >>= 1) v += __shfl_xor_sync(FULLM, v, o);
    return v;
}
__device__ __forceinline__ int wincl(int x, int lane) {
#pragma unroll
    for (int o = 1; o < 32; o <<= 1) {
        int t = __shfl_up_sync(FULLM, x, o);
        if (lane >= o) x += t;
    }
    return x;
}
__device__ __forceinline__ float comp4(float4 v, int h) {
    float r = v.x;
    r = (h == 1) ? v.y : r;
    r = (h == 2) ? v.z : r;
    r = (h == 3) ? v.w : r;
    return r;
}

// ---------------- dtype detect (int32 vs int64 edge_index) ------------------
__global__ void detect_k(const void* ei) {
    int lane = threadIdx.x;
    const int* p = (const int*)ei;
    int bad = 0;
#pragma unroll
    for (int i = 0; i < 8; i++) {
        int idx = lane + i * 32;
        bad |= (p[2 * idx + 1] != 0);
    }
    unsigned any = __ballot_sync(FULLM, bad);
    if (lane == 0) d_is64 = (any == 0) ? 1 : 0;
}

// ---------------- layer1 rank-1 coefficients: cs[h]=W1.a_src1 per head ------
__global__ void coef_k(const float* __restrict__ W1,
                       const float* __restrict__ as1, const float* __restrict__ ad1) {
    int j = threadIdx.x;          // 0..127, warp = head
    float w = W1[j];
    float ps = wredsum(w * as1[j]);
    float pd = wredsum(w * ad1[j]);
    if ((j & 31) == 0) {
        d_cs[j >> 5] = ps;
        d_cd[j >> 5] = pd;
    }
}

// ---------------- CSR build -------------------------------------------------
__global__ void zero_k(int N) {
    int i = blockIdx.x * blockDim.x + threadIdx.x;
    if (i < N) d_deg[i] = 0;
}

__global__ void hist_k(const void* ei, int E, int N) {
    int e = blockIdx.x * blockDim.x + threadIdx.x;
    int tot = E + N;
    if (e >= tot) return;
    int dst;
    if (e < E) {
        if (d_is64) dst = (int)((const long long*)ei)[(long long)E + e];
        else        dst = ((const int*)ei)[E + e];
    } else {
        dst = e - E;  // self loop
    }
    atomicAdd(&d_deg[dst], 1);
}

__global__ void scan1_k(int N) {
    __shared__ int wsum[32];
    int i = blockIdx.x * 1024 + threadIdx.x;
    int lane = threadIdx.x & 31, wid = threadIdx.x >> 5;
    int v = (i < N) ? d_deg[i] : 0;
    int x = wincl(v, lane);
    if (lane == 31) wsum[wid] = x;
    __syncthreads();
    if (wid == 0) wsum[lane] = wincl(wsum[lane], lane);
    __syncthreads();
    int incl = x + (wid ? wsum[wid - 1] : 0);
    if (i < N) d_rowptr[i + 1] = incl;
    if (threadIdx.x == 1023) d_bsum[blockIdx.x] = incl;
}

__global__ void scan2_k(int nb) {
    int lane = threadIdx.x;
    int carry = 0;
    for (int base = 0; base < nb; base += 32) {
        int idx = base + lane;
        int v = (idx < nb) ? d_bsum[idx] : 0;
        int x = wincl(v, lane);
        if (idx < nb) d_boff[idx] = carry + x - v;
        carry += __shfl_sync(FULLM, x, 31);
    }
}

__global__ void scan3_k(int N) {
    int i = blockIdx.x * 1024 + threadIdx.x;
    if (i >= N) return;
    int r = d_rowptr[i + 1] + d_boff[blockIdx.x];
    d_rowptr[i + 1] = r;
    d_cursor[i] = r - d_deg[i];
    if (i == 0) d_rowptr[0] = 0;
}

__global__ void scatter_k(const void* ei, int E, int N) {
    int e = blockIdx.x * blockDim.x + threadIdx.x;
    int tot = E + N;
    if (e >= tot) return;
    int src, dst;
    if (e < E) {
        if (d_is64) {
            const long long* p = (const long long*)ei;
            src = (int)p[e];
            dst = (int)p[(long long)E + e];
        } else {
            const int* p = (const int*)ei;
            src = p[e];
            dst = p[E + e];
        }
    } else {
        src = dst = e - E;
    }
    int pos = atomicAdd(&d_cursor[dst], 1);
    d_col[pos] = src;
}

// ---------------- layer 1: rank-1 fused feature+aggregation -----------------
// out[w,j] = elu( W1[j] * T[head(j)] + b1[j] ),
// T[h] = sum_s alpha_s x[s],  alpha from e = lrelu(x[s]cs[h] + x[w]cd[h]).
__global__ void agg1_k(const float* __restrict__ x,
                       const float* __restrict__ W1, const float* __restrict__ b1,
                       float* __restrict__ z_out, int N) {
    int w = (blockIdx.x * blockDim.x + threadIdx.x) >> 5;
    if (w >= N) return;
    int lane = threadIdx.x & 31;
    int start = d_rowptr[w], end = d_rowptr[w + 1];

    float4 cs = *((const float4*)d_cs);
    float4 cd = *((const float4*)d_cd);
    float xd = x[w];
    float ed0 = xd * cd.x, ed1 = xd * cd.y, ed2 = xd * cd.z, ed3 = xd * cd.w;

    float S0 = 0.f, S1 = 0.f, S2 = 0.f, S3 = 0.f;
    float T0 = 0.f, T1 = 0.f, T2 = 0.f, T3 = 0.f;
    for (int i = start + lane; i < end; i += 32) {
        int s = d_col[i];
        float xs = x[s];
        float w0 = __expf(lrelu(xs * cs.x + ed0));
        float w1 = __expf(lrelu(xs * cs.y + ed1));
        float w2 = __expf(lrelu(xs * cs.z + ed2));
        float w3 = __expf(lrelu(xs * cs.w + ed3));
        S0 += w0; S1 += w1; S2 += w2; S3 += w3;
        T0 = fmaf(w0, xs, T0); T1 = fmaf(w1, xs, T1);
        T2 = fmaf(w2, xs, T2); T3 = fmaf(w3, xs, T3);
    }
    S0 = wredsum(S0); S1 = wredsum(S1); S2 = wredsum(S2); S3 = wredsum(S3);
    T0 = wredsum(T0); T1 = wredsum(T1); T2 = wredsum(T2); T3 = wredsum(T3);

    float t = comp4(make_float4(T0 / S0, T1 / S1, T2 / S2, T3 / S3), lane >> 3);

    float4 W4 = ((const float4*)W1)[lane];
    float4 b4 = ((const float4*)b1)[lane];
    float4 v = make_float4(fmaf(W4.x, t, b4.x), fmaf(W4.y, t, b4.y),
                           fmaf(W4.z, t, b4.z), fmaf(W4.w, t, b4.w));
    v.x = v.x > 0.f ? v.x : expm1f(v.x);
    v.y = v.y > 0.f ? v.y : expm1f(v.y);
    v.z = v.z > 0.f ? v.z : expm1f(v.z);
    v.w = v.w > 0.f ? v.w : expm1f(v.w);
    ((float4*)z_out)[w * 32 + lane] = v;
}

// ---------------- layer 2 feature: h2 = z1 @ W2 (128x128), alphas -----------
#define ZPAD 68
__global__ void gemm_k(const float* __restrict__ zin, const float* __restrict__ W2,
                       const float* __restrict__ as2, const float* __restrict__ ad2,
                       float* __restrict__ h_out, int N) {
    extern __shared__ float smem[];             // [128*128 W][128*ZPAD zt]
    float* Wsm = smem;
    float* zt  = smem + 128 * 128;
    int tid = threadIdx.x;                      // 256 threads
    int c = tid & 31;                           // channels 4c..4c+3
    int g = tid >> 5;                           // node group, nodes g*8..g*8+7
    int head = c >> 3;

    for (int t = tid; t < 128 * 128 / 4; t += 256)
        ((float4*)Wsm)[t] = ((const float4*)W2)[t];

    float4 as4 = ((const float4*)as2)[c];
    float4 ad4 = ((const float4*)ad2)[c];

    for (int tile = blockIdx.x * 64; tile < N; tile += gridDim.x * 64) {
        __syncthreads();
        for (int t = tid; t < 64 * 128; t += 256) {
            int node = t >> 7;
            int k = t & 127;
            int gn = tile + node;
            zt[k * ZPAD + node] = (gn < N) ? zin[gn * 128 + k] : 0.f;
        }
        __syncthreads();

        float4 acc[8];
#pragma unroll
        for (int m = 0; m < 8; m++) acc[m] = make_float4(0.f, 0.f, 0.f, 0.f);

#pragma unroll 2
        for (int k = 0; k < 128; k++) {
            float4 w4 = ((const float4*)(Wsm + k * 128))[c];
            const float* zr = zt + k * ZPAD + g * 8;
            float4 z0 = *((const float4*)zr);
            float4 z1 = *((const float4*)(zr + 4));
            float zm[8] = {z0.x, z0.y, z0.z, z0.w, z1.x, z1.y, z1.z, z1.w};
#pragma unroll
            for (int m = 0; m < 8; m++) {
                acc[m].x = fmaf(zm[m], w4.x, acc[m].x);
                acc[m].y = fmaf(zm[m], w4.y, acc[m].y);
                acc[m].z = fmaf(zm[m], w4.z, acc[m].z);
                acc[m].w = fmaf(zm[m], w4.w, acc[m].w);
            }
        }

#pragma unroll
        for (int m = 0; m < 8; m++) {
            int node = tile + g * 8 + m;
            float ps = acc[m].x * as4.x + acc[m].y * as4.y + acc[m].z * as4.z + acc[m].w * as4.w;
            float pd = acc[m].x * ad4.x + acc[m].y * ad4.y + acc[m].z * ad4.z + acc[m].w * ad4.w;
#pragma unroll
            for (int o = 4; o; o >>= 1) {
                ps += __shfl_xor_sync(FULLM, ps, o);
                pd += __shfl_xor_sync(FULLM, pd, o);
            }
            if (node < N) {
                ((float4*)(h_out + node * 128))[c] = acc[m];
                if ((c & 7) == 0) {
                    d_as[node * 4 + head] = ps;
                    d_ad[node * 4 + head] = pd;
                }
            }
        }
    }
}

// ---------------- layer 2 aggregation, single sweep, warp per dst node ------
// acc = sum_s wgt*h[s], S = sum_s wgt accumulated together; normalize at end.
// fused epilogue: h3 = elu(o+b) . W3 and layer3 alphas.
__global__ void agg2_k(const float* __restrict__ h_in,
                       const float* __restrict__ bias,
                       const float* __restrict__ w3,
                       const float* __restrict__ a3s, const float* __restrict__ a3d,
                       int N) {
    int w = (blockIdx.x * blockDim.x + threadIdx.x) >> 5;
    if (w >= N) return;
    int lane = threadIdx.x & 31;
    int start = d_rowptr[w], end = d_rowptr[w + 1];

    int myh = lane >> 3;
    float adh = comp4(((const float4*)d_ad)[w], myh);

    float sw = 0.f;
    float4 acc = make_float4(0.f, 0.f, 0.f, 0.f);
#pragma unroll 2
    for (int i = start; i < end; i++) {
        int s = d_col[i];
        float4 av = ((const float4*)d_as)[s];
        float wgt = __expf(lrelu(comp4(av, myh) + adh));
        sw += wgt;
        float4 hv = ((const float4*)h_in)[s * 32 + lane];
        acc.x = fmaf(wgt, hv.x, acc.x);
        acc.y = fmaf(wgt, hv.y, acc.y);
        acc.z = fmaf(wgt, hv.z, acc.z);
        acc.w = fmaf(wgt, hv.w, acc.w);
    }
    float inv = 1.f / sw;

    float4 bv = ((const float4*)bias)[lane];
    float4 v = make_float4(fmaf(acc.x, inv, bv.x), fmaf(acc.y, inv, bv.y),
                           fmaf(acc.z, inv, bv.z), fmaf(acc.w, inv, bv.w));
    v.x = v.x > 0.f ? v.x : expm1f(v.x);
    v.y = v.y > 0.f ? v.y : expm1f(v.y);
    v.z = v.z > 0.f ? v.z : expm1f(v.z);
    v.w = v.w > 0.f ? v.w : expm1f(v.w);

    // fused layer-3 feature: h3 = v . W3, alphas
    float4 w4 = ((const float4*)w3)[lane];
    float p = v.x * w4.x + v.y * w4.y + v.z * w4.z + v.w * w4.w;
    p = wredsum(p);
    if (lane == 0) {
        d_h3[w]  = p;
        d_as3[w] = p * a3s[0];
        d_ad3[w] = p * a3d[0];
    }
}

// ---------------- layer 3 aggregation (H=1, C=1), warp per dst node ---------
__global__ void agg3_k(const float* __restrict__ b3, float* __restrict__ out, int N) {
    int w = (blockIdx.x * blockDim.x + threadIdx.x) >> 5;
    if (w >= N) return;
    int lane = threadIdx.x & 31;
    int start = d_rowptr[w], end = d_rowptr[w + 1];
    float adn = d_ad3[w];

    float ss = 0.f, ws = 0.f;
    for (int i = start + lane; i < end; i += 32) {
        int s = d_col[i];
        float wv = __expf(lrelu(d_as3[s] + adn));
        ss += wv;
        ws += wv * d_h3[s];
    }
    ss = wredsum(ss);
    ws = wredsum(ws);
    if (lane == 0) out[w] = ws / ss + b3[0];
}

// ---------------- host launcher ---------------------------------------------
extern "C" void kernel_launch(void* const* d_in, const int* in_sizes, int n_in,
                              void* d_out, int out_size) {
    const float* x   = (const float*)d_in[0];
    const void*  ei  = d_in[1];
    const float* W1  = (const float*)d_in[2];
    const float* as1 = (const float*)d_in[3];
    const float* ad1 = (const float*)d_in[4];
    const float* b1  = (const float*)d_in[5];
    const float* W2  = (const float*)d_in[6];
    const float* as2 = (const float*)d_in[7];
    const float* ad2 = (const float*)d_in[8];
    const float* b2  = (const float*)d_in[9];
    const float* W3  = (const float*)d_in[10];
    const float* a3s = (const float*)d_in[11];
    const float* a3d = (const float*)d_in[12];
    const float* b3  = (const float*)d_in[13];
    float* out = (float*)d_out;

    int N = in_sizes[0];
    int E = in_sizes[1] / 2;
    if (N > NMAX) N = NMAX;
    if (E > EMAX) E = EMAX;
    int tot = E + N;
    int nb = (N + 1023) / 1024;

    float* hA; cudaGetSymbolAddress((void**)&hA, d_hA);
    float* hB; cudaGetSymbolAddress((void**)&hB, d_hB);

    detect_k<<<1, 32>>>(ei);
    coef_k<<<1, 128>>>(W1, as1, ad1);
    zero_k<<<(N + 255) / 256, 256>>>(N);
    hist_k<<<(tot + 255) / 256, 256>>>(ei, E, N);
    scan1_k<<<nb, 1024>>>(N);
    scan2_k<<<1, 32>>>(nb);
    scan3_k<<<nb, 1024>>>(N);
    scatter_k<<<(tot + 255) / 256, 256>>>(ei, E, N);

    int agg_blocks = (N * 32 + 255) / 256;

    // layer 1 (rank-1 factorized: feature transform fused into aggregation)
    agg1_k<<<agg_blocks, 256>>>(x, W1, b1, hB, N);

    // layer 2 (+ fused layer-3 feature)
    size_t smem = (128 * 128 + 128 * ZPAD) * sizeof(float);
    cudaFuncSetAttribute(gemm_k, cudaFuncAttributeMaxDynamicSharedMemorySize, (int)smem);
    gemm_k<<<296, 256, smem>>>(hB, W2, as2, ad2, hA, N);
    agg2_k<<<agg_blocks, 256>>>(hA, b2, W3, a3s, a3d, N);

    // layer 3
    agg3_k<<<agg_blocks, 256>>>(b3, out, N);
}

// round 8
// speedup vs baseline: 2.5153x; 1.0058x over previous
#include <cuda_runtime.h>
#include <cuda_fp16.h>
#include <math.h>

#define NMAX 50000
#define EMAX 800000
#define ETOT (NMAX + EMAX)
#define FULLM 0xffffffffu
#define NBLK ((NMAX + 1023) / 1024)

// ---------------- scratch (static device globals: no allocation allowed) ----
__device__ int   d_is64;
__device__ int   d_deg[NMAX];
__device__ int   d_rowptr[NMAX + 1];
__device__ int   d_cursor[NMAX];
__device__ int   d_bsum[NBLK];
__device__ int   d_boff[NBLK];
__device__ int   d_col[ETOT];
__device__ float d_hA[NMAX * 128];   // h2 buffer (used as fp16, reinterpreted)
__device__ float d_hB[NMAX * 128];   // z1 activation buffer
__device__ float d_as[NMAX * 4];
__device__ float d_ad[NMAX * 4];
__device__ float d_cs[4];            // layer1 rank-1 alpha coefficients
__device__ float d_cd[4];
__device__ float d_h3[NMAX];
__device__ float d_as3[NMAX];
__device__ float d_ad3[NMAX];

// ---------------- helpers ---------------------------------------------------
__device__ __forceinline__ float lrelu(float e) { return e > 0.f ? e : 0.2f * e; }

__device__ __forceinline__ float wredsum(float v) {
#pragma unroll
    for (int o = 16; o; o >>= 1) v += __shfl_xor_sync(FULLM, v, o);
    return v;
}
__device__ __forceinline__ int wincl(int x, int lane) {
#pragma unroll
    for (int o = 1; o < 32; o <<= 1) {
        int t = __shfl_up_sync(FULLM, x, o);
        if (lane >= o) x += t;
    }
    return x;
}
__device__ __forceinline__ float comp4(float4 v, int h) {
    float r = v.x;
    r = (h == 1) ? v.y : r;
    r = (h == 2) ? v.z : r;
    r = (h == 3) ? v.w : r;
    return r;
}

// ---------------- dtype detect (int32 vs int64 edge_index) ------------------
__global__ void detect_k(const void* ei) {
    int lane = threadIdx.x;
    const int* p = (const int*)ei;
    int bad = 0;
#pragma unroll
    for (int i = 0; i < 8; i++) {
        int idx = lane + i * 32;
        bad |= (p[2 * idx + 1] != 0);
    }
    unsigned any = __ballot_sync(FULLM, bad);
    if (lane == 0) d_is64 = (any == 0) ? 1 : 0;
}

// ---------------- layer1 rank-1 coefficients --------------------------------
__global__ void coef_k(const float* __restrict__ W1,
                       const float* __restrict__ as1, const float* __restrict__ ad1) {
    int j = threadIdx.x;          // 0..127, warp = head
    float w = W1[j];
    float ps = wredsum(w * as1[j]);
    float pd = wredsum(w * ad1[j]);
    if ((j & 31) == 0) {
        d_cs[j >> 5] = ps;
        d_cd[j >> 5] = pd;
    }
}

// ---------------- CSR build -------------------------------------------------
__global__ void zero_k(int N) {
    int i = blockIdx.x * blockDim.x + threadIdx.x;
    if (i < N) d_deg[i] = 0;
}

// 4 edges per thread: batched independent loads hide DRAM latency
__global__ void hist_k(const void* ei, int E, int N) {
    int base = (blockIdx.x * blockDim.x + threadIdx.x) * 4;
    int tot = E + N;
    if (base >= tot) return;
    int is64 = d_is64;
    int dsts[4];
#pragma unroll
    for (int u = 0; u < 4; u++) {
        int e = base + u;
        int dst = -1;
        if (e < tot) {
            if (e < E) {
                dst = is64 ? (int)((const long long*)ei)[(long long)E + e]
                           : ((const int*)ei)[E + e];
            } else {
                dst = e - E;
            }
        }
        dsts[u] = dst;
    }
#pragma unroll
    for (int u = 0; u < 4; u++)
        if (dsts[u] >= 0) atomicAdd(&d_deg[dsts[u]], 1);
}

__global__ void scan1_k(int N) {
    __shared__ int wsum[32];
    int i = blockIdx.x * 1024 + threadIdx.x;
    int lane = threadIdx.x & 31, wid = threadIdx.x >> 5;
    int v = (i < N) ? d_deg[i] : 0;
    int x = wincl(v, lane);
    if (lane == 31) wsum[wid] = x;
    __syncthreads();
    if (wid == 0) wsum[lane] = wincl(wsum[lane], lane);
    __syncthreads();
    int incl = x + (wid ? wsum[wid - 1] : 0);
    if (i < N) d_rowptr[i + 1] = incl;
    if (threadIdx.x == 1023) d_bsum[blockIdx.x] = incl;
}

__global__ void scan2_k(int nb) {
    int lane = threadIdx.x;
    int carry = 0;
    for (int base = 0; base < nb; base += 32) {
        int idx = base + lane;
        int v = (idx < nb) ? d_bsum[idx] : 0;
        int x = wincl(v, lane);
        if (idx < nb) d_boff[idx] = carry + x - v;
        carry += __shfl_sync(FULLM, x, 31);
    }
}

__global__ void scan3_k(int N) {
    int i = blockIdx.x * 1024 + threadIdx.x;
    if (i >= N) return;
    int r = d_rowptr[i + 1] + d_boff[blockIdx.x];
    d_rowptr[i + 1] = r;
    d_cursor[i] = r - d_deg[i];
    if (i == 0) d_rowptr[0] = 0;
}

// 4 edges per thread
__global__ void scatter_k(const void* ei, int E, int N) {
    int base = (blockIdx.x * blockDim.x + threadIdx.x) * 4;
    int tot = E + N;
    if (base >= tot) return;
    int is64 = d_is64;
    int srcs[4], dsts[4];
#pragma unroll
    for (int u = 0; u < 4; u++) {
        int e = base + u;
        int src = 0, dst = -1;
        if (e < tot) {
            if (e < E) {
                if (is64) {
                    const long long* p = (const long long*)ei;
                    src = (int)p[e];
                    dst = (int)p[(long long)E + e];
                } else {
                    const int* p = (const int*)ei;
                    src = p[e];
                    dst = p[E + e];
                }
            } else {
                src = dst = e - E;
            }
        }
        srcs[u] = src; dsts[u] = dst;
    }
#pragma unroll
    for (int u = 0; u < 4; u++) {
        if (dsts[u] >= 0) {
            int pos = atomicAdd(&d_cursor[dsts[u]], 1);
            d_col[pos] = srcs[u];
        }
    }
}

// ---------------- layer 1: rank-1 fused feature+aggregation -----------------
__global__ void agg1_k(const float* __restrict__ x,
                       const float* __restrict__ W1, const float* __restrict__ b1,
                       float* __restrict__ z_out, int N) {
    int w = (blockIdx.x * blockDim.x + threadIdx.x) >> 5;
    if (w >= N) return;
    int lane = threadIdx.x & 31;
    int start = d_rowptr[w], end = d_rowptr[w + 1];

    float4 cs = *((const float4*)d_cs);
    float4 cd = *((const float4*)d_cd);
    float xd = x[w];
    float ed0 = xd * cd.x, ed1 = xd * cd.y, ed2 = xd * cd.z, ed3 = xd * cd.w;

    float S0 = 0.f, S1 = 0.f, S2 = 0.f, S3 = 0.f;
    float T0 = 0.f, T1 = 0.f, T2 = 0.f, T3 = 0.f;
    for (int i = start + lane; i < end; i += 32) {
        int s = d_col[i];
        float xs = x[s];
        float w0 = __expf(lrelu(xs * cs.x + ed0));
        float w1 = __expf(lrelu(xs * cs.y + ed1));
        float w2 = __expf(lrelu(xs * cs.z + ed2));
        float w3 = __expf(lrelu(xs * cs.w + ed3));
        S0 += w0; S1 += w1; S2 += w2; S3 += w3;
        T0 = fmaf(w0, xs, T0); T1 = fmaf(w1, xs, T1);
        T2 = fmaf(w2, xs, T2); T3 = fmaf(w3, xs, T3);
    }
    S0 = wredsum(S0); S1 = wredsum(S1); S2 = wredsum(S2); S3 = wredsum(S3);
    T0 = wredsum(T0); T1 = wredsum(T1); T2 = wredsum(T2); T3 = wredsum(T3);

    float t = comp4(make_float4(T0 / S0, T1 / S1, T2 / S2, T3 / S3), lane >> 3);

    float4 W4 = ((const float4*)W1)[lane];
    float4 b4 = ((const float4*)b1)[lane];
    float4 v = make_float4(fmaf(W4.x, t, b4.x), fmaf(W4.y, t, b4.y),
                           fmaf(W4.z, t, b4.z), fmaf(W4.w, t, b4.w));
    v.x = v.x > 0.f ? v.x : expm1f(v.x);
    v.y = v.y > 0.f ? v.y : expm1f(v.y);
    v.z = v.z > 0.f ? v.z : expm1f(v.z);
    v.w = v.w > 0.f ? v.w : expm1f(v.w);
    ((float4*)z_out)[w * 32 + lane] = v;
}

// ---------------- layer 2 feature: h2 = z1 @ W2 (128x128), alphas -----------
// output stored as fp16 (halves the agg2 gather traffic); alphas fp32.
#define ZPAD 68
__global__ void gemm_k(const float* __restrict__ zin, const float* __restrict__ W2,
                       const float* __restrict__ as2, const float* __restrict__ ad2,
                       __half* __restrict__ h_out, int N) {
    extern __shared__ float smem[];             // [128*128 W][128*ZPAD zt]
    float* Wsm = smem;
    float* zt  = smem + 128 * 128;
    int tid = threadIdx.x;                      // 256 threads
    int c = tid & 31;                           // channels 4c..4c+3
    int g = tid >> 5;                           // node group, nodes g*8..g*8+7
    int head = c >> 3;

    for (int t = tid; t < 128 * 128 / 4; t += 256)
        ((float4*)Wsm)[t] = ((const float4*)W2)[t];

    float4 as4 = ((const float4*)as2)[c];
    float4 ad4 = ((const float4*)ad2)[c];

    for (int tile = blockIdx.x * 64; tile < N; tile += gridDim.x * 64) {
        __syncthreads();
        for (int t = tid; t < 64 * 128; t += 256) {
            int node = t >> 7;
            int k = t & 127;
            int gn = tile + node;
            zt[k * ZPAD + node] = (gn < N) ? zin[gn * 128 + k] : 0.f;
        }
        __syncthreads();

        float4 acc[8];
#pragma unroll
        for (int m = 0; m < 8; m++) acc[m] = make_float4(0.f, 0.f, 0.f, 0.f);

#pragma unroll 2
        for (int k = 0; k < 128; k++) {
            float4 w4 = ((const float4*)(Wsm + k * 128))[c];
            const float* zr = zt + k * ZPAD + g * 8;
            float4 z0 = *((const float4*)zr);
            float4 z1 = *((const float4*)(zr + 4));
            float zm[8] = {z0.x, z0.y, z0.z, z0.w, z1.x, z1.y, z1.z, z1.w};
#pragma unroll
            for (int m = 0; m < 8; m++) {
                acc[m].x = fmaf(zm[m], w4.x, acc[m].x);
                acc[m].y = fmaf(zm[m], w4.y, acc[m].y);
                acc[m].z = fmaf(zm[m], w4.z, acc[m].z);
                acc[m].w = fmaf(zm[m], w4.w, acc[m].w);
            }
        }

#pragma unroll
        for (int m = 0; m < 8; m++) {
            int node = tile + g * 8 + m;
            float ps = acc[m].x * as4.x + acc[m].y * as4.y + acc[m].z * as4.z + acc[m].w * as4.w;
            float pd = acc[m].x * ad4.x + acc[m].y * ad4.y + acc[m].z * ad4.z + acc[m].w * ad4.w;
#pragma unroll
            for (int o = 4; o; o >>= 1) {
                ps += __shfl_xor_sync(FULLM, ps, o);
                pd += __shfl_xor_sync(FULLM, pd, o);
            }
            if (node < N) {
                __half2 p0 = __floats2half2_rn(acc[m].x, acc[m].y);
                __half2 p1 = __floats2half2_rn(acc[m].z, acc[m].w);
                uint2 pk;
                pk.x = *(unsigned*)&p0;
                pk.y = *(unsigned*)&p1;
                ((uint2*)(h_out + node * 128))[c] = pk;
                if ((c & 7) == 0) {
                    d_as[node * 4 + head] = ps;
                    d_ad[node * 4 + head] = pd;
                }
            }
        }
    }
}

// ---------------- layer 2 aggregation, single sweep, warp per dst node ------
// fp16 feature gather (fp32 accumulate); fused layer-3 feature epilogue.
__global__ void agg2_k(const __half* __restrict__ h_in,
                       const float* __restrict__ bias,
                       const float* __restrict__ w3,
                       const float* __restrict__ a3s, const float* __restrict__ a3d,
                       int N) {
    int w = (blockIdx.x * blockDim.x + threadIdx.x) >> 5;
    if (w >= N) return;
    int lane = threadIdx.x & 31;
    int start = d_rowptr[w], end = d_rowptr[w + 1];

    int myh = lane >> 3;
    float adh = d_ad[w * 4 + myh];

    float sw = 0.f;
    float4 acc = make_float4(0.f, 0.f, 0.f, 0.f);
#pragma unroll 2
    for (int i = start; i < end; i++) {
        int s = d_col[i];
        float av = d_as[s * 4 + myh];              // 4B broadcast per 8-lane group
        float wgt = __expf(lrelu(av + adh));
        sw += wgt;
        uint2 hv = ((const uint2*)h_in)[s * 32 + lane];
        __half2 h0 = *(__half2*)&hv.x;
        __half2 h1 = *(__half2*)&hv.y;
        float2 f0 = __half22float2(h0);
        float2 f1 = __half22float2(h1);
        acc.x = fmaf(wgt, f0.x, acc.x);
        acc.y = fmaf(wgt, f0.y, acc.y);
        acc.z = fmaf(wgt, f1.x, acc.z);
        acc.w = fmaf(wgt, f1.y, acc.w);
    }
    float inv = 1.f / sw;

    float4 bv = ((const float4*)bias)[lane];
    float4 v = make_float4(fmaf(acc.x, inv, bv.x), fmaf(acc.y, inv, bv.y),
                           fmaf(acc.z, inv, bv.z), fmaf(acc.w, inv, bv.w));
    v.x = v.x > 0.f ? v.x : expm1f(v.x);
    v.y = v.y > 0.f ? v.y : expm1f(v.y);
    v.z = v.z > 0.f ? v.z : expm1f(v.z);
    v.w = v.w > 0.f ? v.w : expm1f(v.w);

    // fused layer-3 feature: h3 = v . W3, alphas
    float4 w4 = ((const float4*)w3)[lane];
    float p = v.x * w4.x + v.y * w4.y + v.z * w4.z + v.w * w4.w;
    p = wredsum(p);
    if (lane == 0) {
        d_h3[w]  = p;
        d_as3[w] = p * a3s[0];
        d_ad3[w] = p * a3d[0];
    }
}

// ---------------- layer 3 aggregation (H=1, C=1), warp per dst node ---------
__global__ void agg3_k(const float* __restrict__ b3, float* __restrict__ out, int N) {
    int w = (blockIdx.x * blockDim.x + threadIdx.x) >> 5;
    if (w >= N) return;
    int lane = threadIdx.x & 31;
    int start = d_rowptr[w], end = d_rowptr[w + 1];
    float adn = d_ad3[w];

    float ss = 0.f, ws = 0.f;
    for (int i = start + lane; i < end; i += 32) {
        int s = d_col[i];
        float wv = __expf(lrelu(d_as3[s] + adn));
        ss += wv;
        ws += wv * d_h3[s];
    }
    ss = wredsum(ss);
    ws = wredsum(ws);
    if (lane == 0) out[w] = ws / ss + b3[0];
}

// ---------------- host launcher ---------------------------------------------
extern "C" void kernel_launch(void* const* d_in, const int* in_sizes, int n_in,
                              void* d_out, int out_size) {
    const float* x   = (const float*)d_in[0];
    const void*  ei  = d_in[1];
    const float* W1  = (const float*)d_in[2];
    const float* as1 = (const float*)d_in[3];
    const float* ad1 = (const float*)d_in[4];
    const float* b1  = (const float*)d_in[5];
    const float* W2  = (const float*)d_in[6];
    const float* as2 = (const float*)d_in[7];
    const float* ad2 = (const float*)d_in[8];
    const float* b2  = (const float*)d_in[9];
    const float* W3  = (const float*)d_in[10];
    const float* a3s = (const float*)d_in[11];
    const float* a3d = (const float*)d_in[12];
    const float* b3  = (const float*)d_in[13];
    float* out = (float*)d_out;

    int N = in_sizes[0];
    int E = in_sizes[1] / 2;
    if (N > NMAX) N = NMAX;
    if (E > EMAX) E = EMAX;
    int tot = E + N;
    int nb = (N + 1023) / 1024;

    float* hA; cudaGetSymbolAddress((void**)&hA, d_hA);
    float* hB; cudaGetSymbolAddress((void**)&hB, d_hB);

    detect_k<<<1, 32>>>(ei);
    coef_k<<<1, 128>>>(W1, as1, ad1);
    zero_k<<<(N + 255) / 256, 256>>>(N);
    int e4_blocks = ((tot + 3) / 4 + 255) / 256;
    hist_k<<<e4_blocks, 256>>>(ei, E, N);
    scan1_k<<<nb, 1024>>>(N);
    scan2_k<<<1, 32>>>(nb);
    scan3_k<<<nb, 1024>>>(N);
    scatter_k<<<e4_blocks, 256>>>(ei, E, N);

    int agg_blocks = (N * 32 + 255) / 256;

    // layer 1 (rank-1 factorized)
    agg1_k<<<agg_blocks, 256>>>(x, W1, b1, hB, N);

    // layer 2 (+ fused layer-3 feature)
    size_t smem = (128 * 128 + 128 * ZPAD) * sizeof(float);
    cudaFuncSetAttribute(gemm_k, cudaFuncAttributeMaxDynamicSharedMemorySize, (int)smem);
    gemm_k<<<296, 256, smem>>>(hB, W2, as2, ad2, (__half*)hA, N);
    agg2_k<<<agg_blocks, 256>>>((const __half*)hA, b2, W3, a3s, a3d, N);

    // layer 3
    agg3_k<<<agg_blocks, 256>>>(b3, out, N);
}

// round 10
// speedup vs baseline: 3.2148x; 1.2781x over previous
#include <cuda_runtime.h>
#include <cuda_fp16.h>
#include <math.h>

#define NMAX 50000
#define EMAX 800000
#define ETOT (NMAX + EMAX)
#define FULLM 0xffffffffu
#define NBLK ((NMAX + 1023) / 1024)
#define APAD 136   // halfs per padded smem row (128 + 8 -> conflict-free frags)

// ---------------- scratch (static device globals: no allocation allowed) ----
__device__ int   d_is64;
__device__ int   d_deg[NMAX];
__device__ int   d_rowptr[NMAX + 1];
__device__ int   d_cursor[NMAX];
__device__ int   d_bsum[NBLK];
__device__ int   d_boff[NBLK];
__device__ int   d_col[ETOT];
__device__ float d_hA[NMAX * 128];   // h2 buffer (fp16, reinterpreted)
__device__ float d_hB[NMAX * 128];   // z1 buffer  (fp16, reinterpreted)
__device__ float d_as[NMAX * 4];
__device__ float d_ad[NMAX * 4];
__device__ float d_cs[4];            // layer1 rank-1 alpha coefficients
__device__ float d_cd[4];
__device__ float d_h3[NMAX];
__device__ float d_as3[NMAX];
__device__ float d_ad3[NMAX];

// ---------------- helpers ---------------------------------------------------
__device__ __forceinline__ float lrelu(float e) { return e > 0.f ? e : 0.2f * e; }

__device__ __forceinline__ float wredsum(float v) {
#pragma unroll
    for (int o = 16; o; o >>= 1) v += __shfl_xor_sync(FULLM, v, o);
    return v;
}
__device__ __forceinline__ int wincl(int x, int lane) {
#pragma unroll
    for (int o = 1; o < 32; o <<= 1) {
        int t = __shfl_up_sync(FULLM, x, o);
        if (lane >= o) x += t;
    }
    return x;
}
__device__ __forceinline__ float comp4(float4 v, int h) {
    float r = v.x;
    r = (h == 1) ? v.y : r;
    r = (h == 2) ? v.z : r;
    r = (h == 3) ? v.w : r;
    return r;
}

// ---------------- dtype detect (int32 vs int64 edge_index) ------------------
__global__ void detect_k(const void* ei) {
    int lane = threadIdx.x;
    const int* p = (const int*)ei;
    int bad = 0;
#pragma unroll
    for (int i = 0; i < 8; i++) {
        int idx = lane + i * 32;
        bad |= (p[2 * idx + 1] != 0);
    }
    unsigned any = __ballot_sync(FULLM, bad);
    if (lane == 0) d_is64 = (any == 0) ? 1 : 0;
}

// ---------------- layer1 rank-1 coefficients --------------------------------
__global__ void coef_k(const float* __restrict__ W1,
                       const float* __restrict__ as1, const float* __restrict__ ad1) {
    int j = threadIdx.x;          // 0..127, warp = head
    float w = W1[j];
    float ps = wredsum(w * as1[j]);
    float pd = wredsum(w * ad1[j]);
    if ((j & 31) == 0) {
        d_cs[j >> 5] = ps;
        d_cd[j >> 5] = pd;
    }
}

// ---------------- CSR build -------------------------------------------------
__global__ void zero_k(int N) {
    int i = blockIdx.x * blockDim.x + threadIdx.x;
    if (i < N) d_deg[i] = 0;
}

__global__ void hist_k(const void* ei, int E, int N) {
    int base = (blockIdx.x * blockDim.x + threadIdx.x) * 4;
    int tot = E + N;
    if (base >= tot) return;
    int is64 = d_is64;
    int dsts[4];
#pragma unroll
    for (int u = 0; u < 4; u++) {
        int e = base + u;
        int dst = -1;
        if (e < tot) {
            if (e < E) {
                dst = is64 ? (int)((const long long*)ei)[(long long)E + e]
                           : ((const int*)ei)[E + e];
            } else {
                dst = e - E;
            }
        }
        dsts[u] = dst;
    }
#pragma unroll
    for (int u = 0; u < 4; u++)
        if (dsts[u] >= 0) atomicAdd(&d_deg[dsts[u]], 1);
}

__global__ void scan1_k(int N) {
    __shared__ int wsum[32];
    int i = blockIdx.x * 1024 + threadIdx.x;
    int lane = threadIdx.x & 31, wid = threadIdx.x >> 5;
    int v = (i < N) ? d_deg[i] : 0;
    int x = wincl(v, lane);
    if (lane == 31) wsum[wid] = x;
    __syncthreads();
    if (wid == 0) wsum[lane] = wincl(wsum[lane], lane);
    __syncthreads();
    int incl = x + (wid ? wsum[wid - 1] : 0);
    if (i < N) d_rowptr[i + 1] = incl;
    if (threadIdx.x == 1023) d_bsum[blockIdx.x] = incl;
}

__global__ void scan2_k(int nb) {
    int lane = threadIdx.x;
    int carry = 0;
    for (int base = 0; base < nb; base += 32) {
        int idx = base + lane;
        int v = (idx < nb) ? d_bsum[idx] : 0;
        int x = wincl(v, lane);
        if (idx < nb) d_boff[idx] = carry + x - v;
        carry += __shfl_sync(FULLM, x, 31);
    }
}

__global__ void scan3_k(int N) {
    int i = blockIdx.x * 1024 + threadIdx.x;
    if (i >= N) return;
    int r = d_rowptr[i + 1] + d_boff[blockIdx.x];
    d_rowptr[i + 1] = r;
    d_cursor[i] = r - d_deg[i];
    if (i == 0) d_rowptr[0] = 0;
}

__global__ void scatter_k(const void* ei, int E, int N) {
    int base = (blockIdx.x * blockDim.x + threadIdx.x) * 4;
    int tot = E + N;
    if (base >= tot) return;
    int is64 = d_is64;
    int srcs[4], dsts[4];
#pragma unroll
    for (int u = 0; u < 4; u++) {
        int e = base + u;
        int src = 0, dst = -1;
        if (e < tot) {
            if (e < E) {
                if (is64) {
                    const long long* p = (const long long*)ei;
                    src = (int)p[e];
                    dst = (int)p[(long long)E + e];
                } else {
                    const int* p = (const int*)ei;
                    src = p[e];
                    dst = p[E + e];
                }
            } else {
                src = dst = e - E;
            }
        }
        srcs[u] = src; dsts[u] = dst;
    }
#pragma unroll
    for (int u = 0; u < 4; u++) {
        if (dsts[u] >= 0) {
            int pos = atomicAdd(&d_cursor[dsts[u]], 1);
            d_col[pos] = srcs[u];
        }
    }
}

// ---------------- layer 1: rank-1 fused feature+aggregation (fp16 out) ------
__global__ void agg1_k(const float* __restrict__ x,
                       const float* __restrict__ W1, const float* __restrict__ b1,
                       __half* __restrict__ z_out, int N) {
    int w = (blockIdx.x * blockDim.x + threadIdx.x) >> 5;
    if (w >= N) return;
    int lane = threadIdx.x & 31;
    int start = d_rowptr[w], end = d_rowptr[w + 1];

    float4 cs = *((const float4*)d_cs);
    float4 cd = *((const float4*)d_cd);
    float xd = x[w];
    float ed0 = xd * cd.x, ed1 = xd * cd.y, ed2 = xd * cd.z, ed3 = xd * cd.w;

    float S0 = 0.f, S1 = 0.f, S2 = 0.f, S3 = 0.f;
    float T0 = 0.f, T1 = 0.f, T2 = 0.f, T3 = 0.f;
    for (int i = start + lane; i < end; i += 32) {
        int s = d_col[i];
        float xs = x[s];
        float w0 = __expf(lrelu(xs * cs.x + ed0));
        float w1 = __expf(lrelu(xs * cs.y + ed1));
        float w2 = __expf(lrelu(xs * cs.z + ed2));
        float w3 = __expf(lrelu(xs * cs.w + ed3));
        S0 += w0; S1 += w1; S2 += w2; S3 += w3;
        T0 = fmaf(w0, xs, T0); T1 = fmaf(w1, xs, T1);
        T2 = fmaf(w2, xs, T2); T3 = fmaf(w3, xs, T3);
    }
    S0 = wredsum(S0); S1 = wredsum(S1); S2 = wredsum(S2); S3 = wredsum(S3);
    T0 = wredsum(T0); T1 = wredsum(T1); T2 = wredsum(T2); T3 = wredsum(T3);

    float t = comp4(make_float4(T0 / S0, T1 / S1, T2 / S2, T3 / S3), lane >> 3);

    float4 W4 = ((const float4*)W1)[lane];
    float4 b4 = ((const float4*)b1)[lane];
    float4 v = make_float4(fmaf(W4.x, t, b4.x), fmaf(W4.y, t, b4.y),
                           fmaf(W4.z, t, b4.z), fmaf(W4.w, t, b4.w));
    v.x = v.x > 0.f ? v.x : expm1f(v.x);
    v.y = v.y > 0.f ? v.y : expm1f(v.y);
    v.z = v.z > 0.f ? v.z : expm1f(v.z);
    v.w = v.w > 0.f ? v.w : expm1f(v.w);

    __half2 p0 = __floats2half2_rn(v.x, v.y);
    __half2 p1 = __floats2half2_rn(v.z, v.w);
    uint2 pk;
    pk.x = *(unsigned*)&p0;
    pk.y = *(unsigned*)&p1;
    ((uint2*)z_out)[w * 32 + lane] = pk;
}

// ---------------- layer 2 GEMM on tensor cores (HMMA m16n8k16) --------------
// h2[50000x128] = z1[50000x128] @ W2[128x128], fp16 in, fp32 acc, fp16 out.
// 296 persistent blocks, 256 thr (8 warps: 4 x 2 over M128 x N128 tile).
__device__ __forceinline__ void mma16816(float c[4], const unsigned a[4],
                                         unsigned b0, unsigned b1) {
    asm volatile(
        "mma.sync.aligned.m16n8k16.row.col.f32.f16.f16.f32 "
        "{%0,%1,%2,%3}, {%4,%5,%6,%7}, {%8,%9}, {%0,%1,%2,%3};\n"
        : "+f"(c[0]), "+f"(c[1]), "+f"(c[2]), "+f"(c[3])
        : "r"(a[0]), "r"(a[1]), "r"(a[2]), "r"(a[3]), "r"(b0), "r"(b1));
}

__global__ void gemm_tc(const __half* __restrict__ zin, const float* __restrict__ W2,
                        __half* __restrict__ h_out, int N) {
    extern __shared__ __half hsm[];           // A:128*APAD, B:128*APAD
    __half* Asm = hsm;
    __half* Bsm = hsm + 128 * APAD;
    int tid = threadIdx.x;
    int lane = tid & 31, warp = tid >> 5;
    int warp_m = warp >> 1, warp_n = warp & 1; // 4 x 2 warp grid

    // W2[k][n] fp32 -> Bsm[n][k] fp16 (once per persistent block)
    for (int idx = tid; idx < 128 * 128; idx += 256) {
        int k = idx >> 7, n = idx & 127;
        Bsm[n * APAD + k] = __float2half(W2[idx]);
    }

    int r0 = warp_m * 32 + (lane >> 2);
    int kcol = (lane & 3) * 2;

    for (int tile = blockIdx.x * 128; tile < N; tile += gridDim.x * 128) {
        __syncthreads();   // Bsm ready / previous Asm reads done
        // z1 tile -> Asm (row m, 128 halfs, padded)
        for (int idx = tid; idx < 128 * 16; idx += 256) {
            int m = idx >> 4, kb = idx & 15;
            int node = tile + m;
            uint4 v = make_uint4(0u, 0u, 0u, 0u);
            if (node < N) v = ((const uint4*)(zin + node * 128))[kb];
            *((uint4*)(Asm + m * APAD + kb * 8)) = v;
        }
        __syncthreads();

        float c[2][8][4];
#pragma unroll
        for (int mt = 0; mt < 2; mt++)
#pragma unroll
            for (int nt = 0; nt < 8; nt++)
#pragma unroll
                for (int q = 0; q < 4; q++) c[mt][nt][q] = 0.f;

#pragma unroll
        for (int ks = 0; ks < 8; ks++) {
            int k0 = ks * 16 + kcol;
            unsigned a[2][4];
#pragma unroll
            for (int mt = 0; mt < 2; mt++) {
                int r = r0 + mt * 16;
                a[mt][0] = *(const unsigned*)(Asm + r * APAD + k0);
                a[mt][1] = *(const unsigned*)(Asm + (r + 8) * APAD + k0);
                a[mt][2] = *(const unsigned*)(Asm + r * APAD + k0 + 8);
                a[mt][3] = *(const unsigned*)(Asm + (r + 8) * APAD + k0 + 8);
            }
#pragma unroll
            for (int nt = 0; nt < 8; nt++) {
                int n = warp_n * 64 + nt * 8 + (lane >> 2);
                unsigned b0 = *(const unsigned*)(Bsm + n * APAD + k0);
                unsigned b1 = *(const unsigned*)(Bsm + n * APAD + k0 + 8);
                mma16816(c[0][nt], a[0], b0, b1);
                mma16816(c[1][nt], a[1], b0, b1);
            }
        }

        // store h2 fp16
#pragma unroll
        for (int mt = 0; mt < 2; mt++) {
            int r = r0 + mt * 16;
            int node0 = tile + r, node1 = tile + r + 8;
#pragma unroll
            for (int nt = 0; nt < 8; nt++) {
                int col = warp_n * 64 + nt * 8 + (lane & 3) * 2;
                if (node0 < N) {
                    __half2 p = __floats2half2_rn(c[mt][nt][0], c[mt][nt][1]);
                    *(__half2*)(h_out + node0 * 128 + col) = p;
                }
                if (node1 < N) {
                    __half2 p = __floats2half2_rn(c[mt][nt][2], c[mt][nt][3]);
                    *(__half2*)(h_out + node1 * 128 + col) = p;
                }
            }
        }
    }
}

// ---------------- layer 2 alphas from fp16 h2 (warp per node) ---------------
__global__ void alpha2_k(const __half* __restrict__ h,
                         const float* __restrict__ as2, const float* __restrict__ ad2,
                         int N) {
    int w = (blockIdx.x * blockDim.x + threadIdx.x) >> 5;
    if (w >= N) return;
    int lane = threadIdx.x & 31;
    uint2 hv = ((const uint2*)h)[w * 32 + lane];
    __half2 h0 = *(__half2*)&hv.x;
    __half2 h1 = *(__half2*)&hv.y;
    float2 f0 = __half22float2(h0);
    float2 f1 = __half22float2(h1);
    float4 a = ((const float4*)as2)[lane];
    float4 d = ((const float4*)ad2)[lane];
    float ps = f0.x * a.x + f0.y * a.y + f1.x * a.z + f1.y * a.w;
    float pd = f0.x * d.x + f0.y * d.y + f1.x * d.z + f1.y * d.w;
#pragma unroll
    for (int o = 1; o < 8; o <<= 1) {
        ps += __shfl_xor_sync(FULLM, ps, o);
        pd += __shfl_xor_sync(FULLM, pd, o);
    }
    if ((lane & 7) == 0) {
        d_as[w * 4 + (lane >> 3)] = ps;
        d_ad[w * 4 + (lane >> 3)] = pd;
    }
}

// ---------------- layer 2 aggregation, single sweep, warp per dst node ------
__global__ void agg2_k(const __half* __restrict__ h_in,
                       const float* __restrict__ bias,
                       const float* __restrict__ w3,
                       const float* __restrict__ a3s, const float* __restrict__ a3d,
                       int N) {
    int w = (blockIdx.x * blockDim.x + threadIdx.x) >> 5;
    if (w >= N) return;
    int lane = threadIdx.x & 31;
    int start = d_rowptr[w], end = d_rowptr[w + 1];

    int myh = lane >> 3;
    float adh = d_ad[w * 4 + myh];

    float sw = 0.f;
    float4 acc = make_float4(0.f, 0.f, 0.f, 0.f);
#pragma unroll 2
    for (int i = start; i < end; i++) {
        int s = d_col[i];
        float av = d_as[s * 4 + myh];
        float wgt = __expf(lrelu(av + adh));
        sw += wgt;
        uint2 hv = ((const uint2*)h_in)[s * 32 + lane];
        __half2 h0 = *(__half2*)&hv.x;
        __half2 h1 = *(__half2*)&hv.y;
        float2 f0 = __half22float2(h0);
        float2 f1 = __half22float2(h1);
        acc.x = fmaf(wgt, f0.x, acc.x);
        acc.y = fmaf(wgt, f0.y, acc.y);
        acc.z = fmaf(wgt, f1.x, acc.z);
        acc.w = fmaf(wgt, f1.y, acc.w);
    }
    float inv = 1.f / sw;

    float4 bv = ((const float4*)bias)[lane];
    float4 v = make_float4(fmaf(acc.x, inv, bv.x), fmaf(acc.y, inv, bv.y),
                           fmaf(acc.z, inv, bv.z), fmaf(acc.w, inv, bv.w));
    v.x = v.x > 0.f ? v.x : expm1f(v.x);
    v.y = v.y > 0.f ? v.y : expm1f(v.y);
    v.z = v.z > 0.f ? v.z : expm1f(v.z);
    v.w = v.w > 0.f ? v.w : expm1f(v.w);

    float4 w4 = ((const float4*)w3)[lane];
    float p = v.x * w4.x + v.y * w4.y + v.z * w4.z + v.w * w4.w;
    p = wredsum(p);
    if (lane == 0) {
        d_h3[w]  = p;
        d_as3[w] = p * a3s[0];
        d_ad3[w] = p * a3d[0];
    }
}

// ---------------- layer 3 aggregation (H=1, C=1), warp per dst node ---------
__global__ void agg3_k(const float* __restrict__ b3, float* __restrict__ out, int N) {
    int w = (blockIdx.x * blockDim.x + threadIdx.x) >> 5;
    if (w >= N) return;
    int lane = threadIdx.x & 31;
    int start = d_rowptr[w], end = d_rowptr[w + 1];
    float adn = d_ad3[w];

    float ss = 0.f, ws = 0.f;
    for (int i = start + lane; i < end; i += 32) {
        int s = d_col[i];
        float wv = __expf(lrelu(d_as3[s] + adn));
        ss += wv;
        ws += wv * d_h3[s];
    }
    ss = wredsum(ss);
    ws = wredsum(ws);
    if (lane == 0) out[w] = ws / ss + b3[0];
}

// ---------------- host launcher ---------------------------------------------
extern "C" void kernel_launch(void* const* d_in, const int* in_sizes, int n_in,
                              void* d_out, int out_size) {
    const float* x   = (const float*)d_in[0];
    const void*  ei  = d_in[1];
    const float* W1  = (const float*)d_in[2];
    const float* as1 = (const float*)d_in[3];
    const float* ad1 = (const float*)d_in[4];
    const float* b1  = (const float*)d_in[5];
    const float* W2  = (const float*)d_in[6];
    const float* as2 = (const float*)d_in[7];
    const float* ad2 = (const float*)d_in[8];
    const float* b2  = (const float*)d_in[9];
    const float* W3  = (const float*)d_in[10];
    const float* a3s = (const float*)d_in[11];
    const float* a3d = (const float*)d_in[12];
    const float* b3  = (const float*)d_in[13];
    float* out = (float*)d_out;

    int N = in_sizes[0];
    int E = in_sizes[1] / 2;
    if (N > NMAX) N = NMAX;
    if (E > EMAX) E = EMAX;
    int tot = E + N;
    int nb = (N + 1023) / 1024;

    float* hA; cudaGetSymbolAddress((void**)&hA, d_hA);
    float* hB; cudaGetSymbolAddress((void**)&hB, d_hB);

    detect_k<<<1, 32>>>(ei);
    coef_k<<<1, 128>>>(W1, as1, ad1);
    zero_k<<<(N + 255) / 256, 256>>>(N);
    int e4_blocks = ((tot + 3) / 4 + 255) / 256;
    hist_k<<<e4_blocks, 256>>>(ei, E, N);
    scan1_k<<<nb, 1024>>>(N);
    scan2_k<<<1, 32>>>(nb);
    scan3_k<<<nb, 1024>>>(N);
    scatter_k<<<e4_blocks, 256>>>(ei, E, N);

    int agg_blocks = (N * 32 + 255) / 256;

    // layer 1 (rank-1 factorized, fp16 z1 out)
    agg1_k<<<agg_blocks, 256>>>(x, W1, b1, (__half*)hB, N);

    // layer 2: tensor-core GEMM + alphas + aggregation (fused layer-3 feat)
    size_t smem = 2 * 128 * APAD * sizeof(__half);
    cudaFuncSetAttribute(gemm_tc, cudaFuncAttributeMaxDynamicSharedMemorySize, (int)smem);
    gemm_tc<<<296, 256, smem>>>((const __half*)hB, W2, (__half*)hA, N);
    alpha2_k<<<agg_blocks, 256>>>((const __half*)hA, as2, ad2, N);
    agg2_k<<<agg_blocks, 256>>>((const __half*)hA, b2, W3, a3s, a3d, N);

    // layer 3
    agg3_k<<<agg_blocks, 256>>>(b3, out, N);
}

// round 11
// speedup vs baseline: 3.2165x; 1.0005x over previous
#include <cuda_runtime.h>
#include <cuda_fp16.h>
#include <math.h>

#define NMAX 50000
#define EMAX 800000
#define ETOT (NMAX + EMAX)
#define FULLM 0xffffffffu
#define NBLK ((NMAX + 1023) / 1024)
#define APAD 136   // halfs per padded smem row (128 + 8 -> conflict-free frags)

// ---------------- scratch (static device globals: no allocation allowed) ----
__device__ int   d_is64;
__device__ int   d_deg[NMAX];
__device__ int   d_rowptr[NMAX + 1];
__device__ int   d_cursor[NMAX];
__device__ int   d_tstate[NBLK];     // decoupled-lookback: 0 none, 1 agg, 2 incl
__device__ int   d_tagg[NBLK];
__device__ int   d_tinc[NBLK];
__device__ int   d_col[ETOT];
__device__ float d_hA[NMAX * 128];   // h2 buffer (fp16, reinterpreted)
__device__ float d_hB[NMAX * 128];   // z1 buffer  (fp16, reinterpreted)
__device__ float d_as[NMAX * 4];
__device__ float d_ad[NMAX * 4];
__device__ float d_cs[4];            // layer1 rank-1 alpha coefficients
__device__ float d_cd[4];
__device__ float2 d_p3[NMAX];        // packed {h3, as3}
__device__ float d_ad3[NMAX];

// ---------------- helpers ---------------------------------------------------
__device__ __forceinline__ float lrelu(float e) { return e > 0.f ? e : 0.2f * e; }

__device__ __forceinline__ float wredsum(float v) {
#pragma unroll
    for (int o = 16; o; o >>= 1) v += __shfl_xor_sync(FULLM, v, o);
    return v;
}
__device__ __forceinline__ int wincl(int x, int lane) {
#pragma unroll
    for (int o = 1; o < 32; o <<= 1) {
        int t = __shfl_up_sync(FULLM, x, o);
        if (lane >= o) x += t;
    }
    return x;
}
__device__ __forceinline__ float comp4(float4 v, int h) {
    float r = v.x;
    r = (h == 1) ? v.y : r;
    r = (h == 2) ? v.z : r;
    r = (h == 3) ? v.w : r;
    return r;
}

// ---------------- fused init: detect dtype + coef + zero deg + scan flags ---
__global__ void init_k(const void* ei, const float* __restrict__ W1,
                       const float* __restrict__ as1, const float* __restrict__ ad1,
                       int N) {
    int gtid = blockIdx.x * blockDim.x + threadIdx.x;
    for (int i = gtid; i < N; i += gridDim.x * blockDim.x) d_deg[i] = 0;
    if (gtid < NBLK) d_tstate[gtid] = 0;

    if (blockIdx.x == 0) {
        if (threadIdx.x < 32) {                      // warp 0: dtype detect
            int lane = threadIdx.x;
            const int* p = (const int*)ei;
            int bad = 0;
#pragma unroll
            for (int i = 0; i < 8; i++)
                bad |= (p[2 * (lane + i * 32) + 1] != 0);
            unsigned any = __ballot_sync(FULLM, bad);
            if (lane == 0) d_is64 = (any == 0) ? 1 : 0;
        } else if (threadIdx.x < 160) {              // warps 1-4: layer1 coefs
            int j = threadIdx.x - 32;                // 0..127, warp = head
            float w = W1[j];
            float ps = wredsum(w * as1[j]);
            float pd = wredsum(w * ad1[j]);
            if ((j & 31) == 0) {
                d_cs[j >> 5] = ps;
                d_cd[j >> 5] = pd;
            }
        }
    }
}

// ---------------- CSR build -------------------------------------------------
__global__ void hist_k(const void* ei, int E, int N) {
    int base = (blockIdx.x * blockDim.x + threadIdx.x) * 4;
    int tot = E + N;
    if (base >= tot) return;
    int is64 = d_is64;
    int dsts[4];
#pragma unroll
    for (int u = 0; u < 4; u++) {
        int e = base + u;
        int dst = -1;
        if (e < tot) {
            if (e < E) {
                dst = is64 ? (int)((const long long*)ei)[(long long)E + e]
                           : ((const int*)ei)[E + e];
            } else {
                dst = e - E;
            }
        }
        dsts[u] = dst;
    }
#pragma unroll
    for (int u = 0; u < 4; u++)
        if (dsts[u] >= 0) atomicAdd(&d_deg[dsts[u]], 1);
}

// single-pass scan, decoupled lookback (NBLK=49 blocks, all resident -> safe)
__global__ void scan_k(int N) {
    __shared__ int wsum[32];
    __shared__ int s_excl;
    int b = blockIdx.x;
    int i = b * 1024 + threadIdx.x;
    int lane = threadIdx.x & 31, wid = threadIdx.x >> 5;
    int v = (i < N) ? d_deg[i] : 0;
    int x = wincl(v, lane);
    if (lane == 31) wsum[wid] = x;
    __syncthreads();
    if (wid == 0) wsum[lane] = wincl(wsum[lane], lane);
    __syncthreads();
    int incl = x + (wid ? wsum[wid - 1] : 0);

    if (threadIdx.x == 0) {
        int agg = wsum[31];
        volatile int* st = d_tstate;
        if (b == 0) {
            d_tinc[0] = agg;
            __threadfence();
            st[0] = 2;
            s_excl = 0;
        } else {
            d_tagg[b] = agg;
            __threadfence();
            st[b] = 1;
            int run = 0;
            for (int j = b - 1; j >= 0; j--) {
                int s;
                do { s = st[j]; } while (s < 1);
                if (s == 2) { run += ((volatile int*)d_tinc)[j]; break; }
                run += ((volatile int*)d_tagg)[j];
            }
            d_tinc[b] = run + agg;
            __threadfence();
            st[b] = 2;
            s_excl = run;
        }
    }
    __syncthreads();
    int excl = s_excl;
    if (i < N) {
        int r = incl + excl;
        d_rowptr[i + 1] = r;
        d_cursor[i] = r - v;
    }
    if (i == 0) d_rowptr[0] = 0;
}

__global__ void scatter_k(const void* ei, int E, int N) {
    int base = (blockIdx.x * blockDim.x + threadIdx.x) * 4;
    int tot = E + N;
    if (base >= tot) return;
    int is64 = d_is64;
    int srcs[4], dsts[4];
#pragma unroll
    for (int u = 0; u < 4; u++) {
        int e = base + u;
        int src = 0, dst = -1;
        if (e < tot) {
            if (e < E) {
                if (is64) {
                    const long long* p = (const long long*)ei;
                    src = (int)p[e];
                    dst = (int)p[(long long)E + e];
                } else {
                    const int* p = (const int*)ei;
                    src = p[e];
                    dst = p[E + e];
                }
            } else {
                src = dst = e - E;
            }
        }
        srcs[u] = src; dsts[u] = dst;
    }
#pragma unroll
    for (int u = 0; u < 4; u++) {
        if (dsts[u] >= 0) {
            int pos = atomicAdd(&d_cursor[dsts[u]], 1);
            d_col[pos] = srcs[u];
        }
    }
}

// ---------------- layer 1: rank-1 fused feature+aggregation (fp16 out) ------
__global__ void agg1_k(const float* __restrict__ x,
                       const float* __restrict__ W1, const float* __restrict__ b1,
                       __half* __restrict__ z_out, int N) {
    int w = (blockIdx.x * blockDim.x + threadIdx.x) >> 5;
    if (w >= N) return;
    int lane = threadIdx.x & 31;
    int start = d_rowptr[w], end = d_rowptr[w + 1];

    float4 cs = *((const float4*)d_cs);
    float4 cd = *((const float4*)d_cd);
    float xd = x[w];
    float ed0 = xd * cd.x, ed1 = xd * cd.y, ed2 = xd * cd.z, ed3 = xd * cd.w;

    float S0 = 0.f, S1 = 0.f, S2 = 0.f, S3 = 0.f;
    float T0 = 0.f, T1 = 0.f, T2 = 0.f, T3 = 0.f;
    for (int i = start + lane; i < end; i += 32) {
        int s = d_col[i];
        float xs = x[s];
        float w0 = __expf(lrelu(xs * cs.x + ed0));
        float w1 = __expf(lrelu(xs * cs.y + ed1));
        float w2 = __expf(lrelu(xs * cs.z + ed2));
        float w3 = __expf(lrelu(xs * cs.w + ed3));
        S0 += w0; S1 += w1; S2 += w2; S3 += w3;
        T0 = fmaf(w0, xs, T0); T1 = fmaf(w1, xs, T1);
        T2 = fmaf(w2, xs, T2); T3 = fmaf(w3, xs, T3);
    }
    S0 = wredsum(S0); S1 = wredsum(S1); S2 = wredsum(S2); S3 = wredsum(S3);
    T0 = wredsum(T0); T1 = wredsum(T1); T2 = wredsum(T2); T3 = wredsum(T3);

    float t = comp4(make_float4(T0 / S0, T1 / S1, T2 / S2, T3 / S3), lane >> 3);

    float4 W4 = ((const float4*)W1)[lane];
    float4 b4 = ((const float4*)b1)[lane];
    float4 v = make_float4(fmaf(W4.x, t, b4.x), fmaf(W4.y, t, b4.y),
                           fmaf(W4.z, t, b4.z), fmaf(W4.w, t, b4.w));
    v.x = v.x > 0.f ? v.x : expm1f(v.x);
    v.y = v.y > 0.f ? v.y : expm1f(v.y);
    v.z = v.z > 0.f ? v.z : expm1f(v.z);
    v.w = v.w > 0.f ? v.w : expm1f(v.w);

    __half2 p0 = __floats2half2_rn(v.x, v.y);
    __half2 p1 = __floats2half2_rn(v.z, v.w);
    uint2 pk;
    pk.x = *(unsigned*)&p0;
    pk.y = *(unsigned*)&p1;
    ((uint2*)z_out)[w * 32 + lane] = pk;
}

// ---------------- layer 2 GEMM on tensor cores + fused alphas ---------------
// h2 = z1 @ W2 (fp16 in, fp32 acc, fp16 out). Alphas computed from fp32
// accumulators in the epilogue (quad-shuffle reduce), killing alpha2_k.
__device__ __forceinline__ void mma16816(float c[4], const unsigned a[4],
                                         unsigned b0, unsigned b1) {
    asm volatile(
        "mma.sync.aligned.m16n8k16.row.col.f32.f16.f16.f32 "
        "{%0,%1,%2,%3}, {%4,%5,%6,%7}, {%8,%9}, {%0,%1,%2,%3};\n"
        : "+f"(c[0]), "+f"(c[1]), "+f"(c[2]), "+f"(c[3])
        : "r"(a[0]), "r"(a[1]), "r"(a[2]), "r"(a[3]), "r"(b0), "r"(b1));
}

__global__ void gemm_tc(const __half* __restrict__ zin, const float* __restrict__ W2,
                        const float* __restrict__ as2, const float* __restrict__ ad2,
                        __half* __restrict__ h_out, int N) {
    extern __shared__ __half hsm[];           // A:128*APAD, B:128*APAD
    __half* Asm = hsm;
    __half* Bsm = hsm + 128 * APAD;
    int tid = threadIdx.x;
    int lane = tid & 31, warp = tid >> 5;
    int warp_m = warp >> 1, warp_n = warp & 1; // 4 x 2 warp grid

    for (int idx = tid; idx < 128 * 128; idx += 256) {
        int k = idx >> 7, n = idx & 127;
        Bsm[n * APAD + k] = __float2half(W2[idx]);
    }

    int r0 = warp_m * 32 + (lane >> 2);
    int kcol = (lane & 3) * 2;
    int headA = warp_n * 2, headB = warp_n * 2 + 1;

    for (int tile = blockIdx.x * 128; tile < N; tile += gridDim.x * 128) {
        __syncthreads();
        for (int idx = tid; idx < 128 * 16; idx += 256) {
            int m = idx >> 4, kb = idx & 15;
            int node = tile + m;
            uint4 v = make_uint4(0u, 0u, 0u, 0u);
            if (node < N) v = ((const uint4*)(zin + node * 128))[kb];
            *((uint4*)(Asm + m * APAD + kb * 8)) = v;
        }
        __syncthreads();

        float c[2][8][4];
#pragma unroll
        for (int mt = 0; mt < 2; mt++)
#pragma unroll
            for (int nt = 0; nt < 8; nt++)
#pragma unroll
                for (int q = 0; q < 4; q++) c[mt][nt][q] = 0.f;

#pragma unroll
        for (int ks = 0; ks < 8; ks++) {
            int k0 = ks * 16 + kcol;
            unsigned a[2][4];
#pragma unroll
            for (int mt = 0; mt < 2; mt++) {
                int r = r0 + mt * 16;
                a[mt][0] = *(const unsigned*)(Asm + r * APAD + k0);
                a[mt][1] = *(const unsigned*)(Asm + (r + 8) * APAD + k0);
                a[mt][2] = *(const unsigned*)(Asm + r * APAD + k0 + 8);
                a[mt][3] = *(const unsigned*)(Asm + (r + 8) * APAD + k0 + 8);
            }
#pragma unroll
            for (int nt = 0; nt < 8; nt++) {
                int n = warp_n * 64 + nt * 8 + (lane >> 2);
                unsigned b0 = *(const unsigned*)(Bsm + n * APAD + k0);
                unsigned b1 = *(const unsigned*)(Bsm + n * APAD + k0 + 8);
                mma16816(c[0][nt], a[0], b0, b1);
                mma16816(c[1][nt], a[1], b0, b1);
            }
        }

        // epilogue: store fp16 h2 + alphas from fp32 accumulators
#pragma unroll
        for (int mt = 0; mt < 2; mt++) {
#pragma unroll
            for (int half = 0; half < 2; half++) {
                int r = r0 + mt * 16 + half * 8;
                int node = tile + r;
                float psA = 0.f, pdA = 0.f, psB = 0.f, pdB = 0.f;
#pragma unroll
                for (int nt = 0; nt < 8; nt++) {
                    int col = warp_n * 64 + nt * 8 + (lane & 3) * 2;
                    float c0 = c[mt][nt][half * 2];
                    float c1 = c[mt][nt][half * 2 + 1];
                    float2 av = *(const float2*)(as2 + col);
                    float2 dv = *(const float2*)(ad2 + col);
                    float ps = c0 * av.x + c1 * av.y;
                    float pd = c0 * dv.x + c1 * dv.y;
                    if (nt < 4) { psA += ps; pdA += pd; }
                    else        { psB += ps; pdB += pd; }
                    if (node < N) {
                        __half2 p = __floats2half2_rn(c0, c1);
                        *(__half2*)(h_out + node * 128 + col) = p;
                    }
                }
                psA += __shfl_xor_sync(FULLM, psA, 1);
                psA += __shfl_xor_sync(FULLM, psA, 2);
                psB += __shfl_xor_sync(FULLM, psB, 1);
                psB += __shfl_xor_sync(FULLM, psB, 2);
                pdA += __shfl_xor_sync(FULLM, pdA, 1);
                pdA += __shfl_xor_sync(FULLM, pdA, 2);
                pdB += __shfl_xor_sync(FULLM, pdB, 1);
                pdB += __shfl_xor_sync(FULLM, pdB, 2);
                if ((lane & 3) == 0 && node < N) {
                    d_as[node * 4 + headA] = psA;
                    d_as[node * 4 + headB] = psB;
                    d_ad[node * 4 + headA] = pdA;
                    d_ad[node * 4 + headB] = pdB;
                }
            }
        }
    }
}

// ---------------- layer 2 aggregation, single sweep, warp per dst node ------
__global__ void agg2_k(const __half* __restrict__ h_in,
                       const float* __restrict__ bias,
                       const float* __restrict__ w3,
                       const float* __restrict__ a3s, const float* __restrict__ a3d,
                       int N) {
    int w = (blockIdx.x * blockDim.x + threadIdx.x) >> 5;
    if (w >= N) return;
    int lane = threadIdx.x & 31;
    int start = d_rowptr[w], end = d_rowptr[w + 1];

    int myh = lane >> 3;
    float adh = d_ad[w * 4 + myh];

    float sw = 0.f;
    float4 acc = make_float4(0.f, 0.f, 0.f, 0.f);
#pragma unroll 2
    for (int i = start; i < end; i++) {
        int s = d_col[i];
        float av = d_as[s * 4 + myh];
        float wgt = __expf(lrelu(av + adh));
        sw += wgt;
        uint2 hv = ((const uint2*)h_in)[s * 32 + lane];
        __half2 h0 = *(__half2*)&hv.x;
        __half2 h1 = *(__half2*)&hv.y;
        float2 f0 = __half22float2(h0);
        float2 f1 = __half22float2(h1);
        acc.x = fmaf(wgt, f0.x, acc.x);
        acc.y = fmaf(wgt, f0.y, acc.y);
        acc.z = fmaf(wgt, f1.x, acc.z);
        acc.w = fmaf(wgt, f1.y, acc.w);
    }
    float inv = 1.f / sw;

    float4 bv = ((const float4*)bias)[lane];
    float4 v = make_float4(fmaf(acc.x, inv, bv.x), fmaf(acc.y, inv, bv.y),
                           fmaf(acc.z, inv, bv.z), fmaf(acc.w, inv, bv.w));
    v.x = v.x > 0.f ? v.x : expm1f(v.x);
    v.y = v.y > 0.f ? v.y : expm1f(v.y);
    v.z = v.z > 0.f ? v.z : expm1f(v.z);
    v.w = v.w > 0.f ? v.w : expm1f(v.w);

    float4 w4 = ((const float4*)w3)[lane];
    float p = v.x * w4.x + v.y * w4.y + v.z * w4.z + v.w * w4.w;
    p = wredsum(p);
    if (lane == 0) {
        d_p3[w]  = make_float2(p, p * a3s[0]);  // {h3, as3} packed: 1 sector/edge
        d_ad3[w] = p * a3d[0];
    }
}

// ---------------- layer 3 aggregation (H=1, C=1), warp per dst node ---------
__global__ void agg3_k(const float* __restrict__ b3, float* __restrict__ out, int N) {
    int w = (blockIdx.x * blockDim.x + threadIdx.x) >> 5;
    if (w >= N) return;
    int lane = threadIdx.x & 31;
    int start = d_rowptr[w], end = d_rowptr[w + 1];
    float adn = d_ad3[w];

    float ss = 0.f, ws = 0.f;
    for (int i = start + lane; i < end; i += 32) {
        int s = d_col[i];
        float2 pv = d_p3[s];
        float wv = __expf(lrelu(pv.y + adn));
        ss += wv;
        ws += wv * pv.x;
    }
    ss = wredsum(ss);
    ws = wredsum(ws);
    if (lane == 0) out[w] = ws / ss + b3[0];
}

// ---------------- host launcher ---------------------------------------------
extern "C" void kernel_launch(void* const* d_in, const int* in_sizes, int n_in,
                              void* d_out, int out_size) {
    const float* x   = (const float*)d_in[0];
    const void*  ei  = d_in[1];
    const float* W1  = (const float*)d_in[2];
    const float* as1 = (const float*)d_in[3];
    const float* ad1 = (const float*)d_in[4];
    const float* b1  = (const float*)d_in[5];
    const float* W2  = (const float*)d_in[6];
    const float* as2 = (const float*)d_in[7];
    const float* ad2 = (const float*)d_in[8];
    const float* b2  = (const float*)d_in[9];
    const float* W3  = (const float*)d_in[10];
    const float* a3s = (const float*)d_in[11];
    const float* a3d = (const float*)d_in[12];
    const float* b3  = (const float*)d_in[13];
    float* out = (float*)d_out;

    int N = in_sizes[0];
    int E = in_sizes[1] / 2;
    if (N > NMAX) N = NMAX;
    if (E > EMAX) E = EMAX;
    int tot = E + N;

    float* hA; cudaGetSymbolAddress((void**)&hA, d_hA);
    float* hB; cudaGetSymbolAddress((void**)&hB, d_hB);

    init_k<<<(N + 255) / 256, 256>>>(ei, W1, as1, ad1, N);
    int e4_blocks = ((tot + 3) / 4 + 255) / 256;
    hist_k<<<e4_blocks, 256>>>(ei, E, N);
    scan_k<<<NBLK, 1024>>>(N);
    scatter_k<<<e4_blocks, 256>>>(ei, E, N);

    int agg_blocks = (N * 32 + 255) / 256;

    // layer 1 (rank-1 factorized, fp16 z1 out)
    agg1_k<<<agg_blocks, 256>>>(x, W1, b1, (__half*)hB, N);

    // layer 2: tensor-core GEMM (+fused alphas) + aggregation (+layer-3 feat)
    size_t smem = 2 * 128 * APAD * sizeof(__half);
    cudaFuncSetAttribute(gemm_tc, cudaFuncAttributeMaxDynamicSharedMemorySize, (int)smem);
    gemm_tc<<<296, 256, smem>>>((const __half*)hB, W2, as2, ad2, (__half*)hA, N);
    agg2_k<<<agg_blocks, 256>>>((const __half*)hA, b2, W3, a3s, a3d, N);

    // layer 3
    agg3_k<<<agg_blocks, 256>>>(b3, out, N);
}